// round 3
// baseline (speedup 1.0000x reference)
#include <cuda_runtime.h>
#include <math.h>

#define BATCH  2
#define SEQ    2048
#define DMODEL 256
#define DINNER 512
#define DSTATE 16
#define NTOK   (BATCH*SEQ)   // 4096

// ---------------- scratch (no allocations allowed) ----------------
__device__ float g_hn[NTOK*DMODEL];       // rmsnorm output
__device__ float g_xz[NTOK*2*DINNER];     // in_proj output
__device__ float g_xc[NTOK*DINNER];       // conv+silu output
__device__ float g_dbl[NTOK*48];          // x_proj output (dt|B|C)
__device__ float g_delta[NTOK*DINNER];    // softplus(dt_proj)
__device__ float g_yact[NTOK*DINNER];     // y * silu(z)

// ---------------- 1) RMSNorm: coalesced transposed reads + smem transpose ----
__global__ __launch_bounds__(256) void rmsnorm_kernel(
    const float* __restrict__ x, const float* __restrict__ nw)
{
    int l0 = blockIdx.x * 32;            // 128 blocks, 32 tokens each
    int b  = l0 >> 11;
    int lb = l0 & 2047;
    int w    = threadIdx.x >> 5;
    int lane = threadIdx.x & 31;

    __shared__ float st[256*33];         // [c][t], stride 33 conflict-free
    __shared__ float ssum[32][9];
    __shared__ float rs[32];

    const float* xb = x + (size_t)b * DMODEL * SEQ + lb + lane;

    float vals[32];
    float ss = 0.f;
    #pragma unroll
    for (int ci = 0; ci < 32; ci++) {
        int c = ci*8 + w;
        float v = xb[(size_t)c * SEQ];   // coalesced over lane
        vals[ci] = v;
        ss += v*v;
    }
    ssum[lane][w] = ss;
    __syncthreads();
    if (threadIdx.x < 32) {
        float tot = 0.f;
        #pragma unroll
        for (int j = 0; j < 8; j++) tot += ssum[threadIdx.x][j];
        rs[threadIdx.x] = rsqrtf(tot * (1.0f/DMODEL) + 1e-5f);
    }
    // stage values into [c][t]
    #pragma unroll
    for (int ci = 0; ci < 32; ci++)
        st[(ci*8 + w)*33 + lane] = vals[ci];
    __syncthreads();

    // write hn[token][c] coalesced
    #pragma unroll
    for (int p = 0; p < 4; p++) {
        int t = (threadIdx.x >> 5) + p*8;
        float r = rs[t];
        float* orow = g_hn + (size_t)(l0 + t)*DMODEL;
        #pragma unroll
        for (int j = 0; j < 8; j++) {
            int c = lane + j*32;
            orow[c] = st[c*33 + t] * r * nw[c];
        }
    }
}

// ---------------- tf32 tensor-core GEMM:  C = A(MxK) * B(NxK)^T ----------------
// BM=128: 8 warps 4m x 2n (warp tile 32x32). BM=32: 8 warps 1m x 8n (32x8).
// Register-level software pipeline over 32-wide K chunks.
// MODE 0: row-major store. MODE 1: out_proj epilogue (smem transpose + residual).
__device__ __forceinline__ unsigned f2tf(float v) {
    unsigned o; asm("cvt.rna.tf32.f32 %0, %1;" : "=r"(o) : "f"(v)); return o;
}

template<int MODE, int BM>
__global__ __launch_bounds__(256) void mma_tn(
    const float* __restrict__ A, const float* __restrict__ B,
    float* __restrict__ C, int M, int N, int K,
    const float* __restrict__ resid)
{
    constexpr int ANUM = BM/32;                 // A float4 loads per thread
    constexpr int NT   = (BM==128) ? 4 : 1;     // n sub-tiles per warp
    constexpr int SW   = (MODE==1) ? 64*132 : (BM*36 + 64*36);
    __shared__ __align__(16) unsigned sm[SW];
    unsigned (*As)[36] = (unsigned(*)[36])sm;
    unsigned (*Bs)[36] = (unsigned(*)[36])(sm + BM*36);

    int tid  = threadIdx.x;
    int lane = tid & 31, w = tid >> 5;
    int wm = (BM==128) ? (w & 3) : 0;
    int wn = (BM==128) ? (w >> 2) : w;
    int rowBase = blockIdx.x * BM;
    int colBase = blockIdx.y * 64;

    float acc[2][NT][4];
    #pragma unroll
    for (int mt = 0; mt < 2; mt++)
        #pragma unroll
        for (int nt = 0; nt < NT; nt++)
            #pragma unroll
            for (int q = 0; q < 4; q++) acc[mt][nt][q] = 0.f;

    int lr = tid >> 3;          // 0..31
    int lc = (tid & 7) * 4;

    float4 ra[ANUM], rb[2];
    const float* Ab = A + (size_t)(rowBase + lr)*K + lc;
    int bn0 = colBase + lr;

    // ---- prologue: chunk 0 ----
    #pragma unroll
    for (int i = 0; i < ANUM; i++) ra[i] = *(const float4*)(Ab + (size_t)i*32*K);
    #pragma unroll
    for (int i = 0; i < 2; i++) {
        int bn = bn0 + i*32;
        rb[i] = (bn < N) ? *(const float4*)(B + (size_t)bn*K + lc)
                         : make_float4(0.f,0.f,0.f,0.f);
    }
    #pragma unroll
    for (int i = 0; i < ANUM; i++)
        *(uint4*)&As[lr + i*32][lc] = make_uint4(f2tf(ra[i].x), f2tf(ra[i].y), f2tf(ra[i].z), f2tf(ra[i].w));
    #pragma unroll
    for (int i = 0; i < 2; i++)
        *(uint4*)&Bs[lr + i*32][lc] = make_uint4(f2tf(rb[i].x), f2tf(rb[i].y), f2tf(rb[i].z), f2tf(rb[i].w));
    __syncthreads();

    for (int kt = 32; kt <= K; kt += 32) {
        // issue global loads for next chunk
        if (kt < K) {
            #pragma unroll
            for (int i = 0; i < ANUM; i++) ra[i] = *(const float4*)(Ab + kt + (size_t)i*32*K);
            #pragma unroll
            for (int i = 0; i < 2; i++) {
                int bn = bn0 + i*32;
                rb[i] = (bn < N) ? *(const float4*)(B + (size_t)bn*K + kt + lc)
                                 : make_float4(0.f,0.f,0.f,0.f);
            }
        }
        // compute current chunk from smem
        #pragma unroll
        for (int kk = 0; kk < 32; kk += 8) {
            unsigned a[2][4], bf[NT][2];
            #pragma unroll
            for (int mt = 0; mt < 2; mt++) {
                int r = wm*32 + mt*16 + (lane >> 2);
                int c = kk + (lane & 3);
                a[mt][0] = As[r  ][c  ];
                a[mt][1] = As[r+8][c  ];
                a[mt][2] = As[r  ][c+4];
                a[mt][3] = As[r+8][c+4];
            }
            #pragma unroll
            for (int nt = 0; nt < NT; nt++) {
                int nb = wn*(8*NT) + nt*8 + (lane >> 2);
                int c = kk + (lane & 3);
                bf[nt][0] = Bs[nb][c];
                bf[nt][1] = Bs[nb][c+4];
            }
            #pragma unroll
            for (int mt = 0; mt < 2; mt++)
                #pragma unroll
                for (int nt = 0; nt < NT; nt++)
                    asm volatile(
                        "mma.sync.aligned.m16n8k8.row.col.f32.tf32.tf32.f32 "
                        "{%0,%1,%2,%3}, {%4,%5,%6,%7}, {%8,%9}, {%0,%1,%2,%3};"
                        : "+f"(acc[mt][nt][0]), "+f"(acc[mt][nt][1]),
                          "+f"(acc[mt][nt][2]), "+f"(acc[mt][nt][3])
                        : "r"(a[mt][0]), "r"(a[mt][1]), "r"(a[mt][2]), "r"(a[mt][3]),
                          "r"(bf[nt][0]), "r"(bf[nt][1]));
        }
        if (kt < K) {
            __syncthreads();
            #pragma unroll
            for (int i = 0; i < ANUM; i++)
                *(uint4*)&As[lr + i*32][lc] = make_uint4(f2tf(ra[i].x), f2tf(ra[i].y), f2tf(ra[i].z), f2tf(ra[i].w));
            #pragma unroll
            for (int i = 0; i < 2; i++)
                *(uint4*)&Bs[lr + i*32][lc] = make_uint4(f2tf(rb[i].x), f2tf(rb[i].y), f2tf(rb[i].z), f2tf(rb[i].w));
            __syncthreads();
        }
    }

    if (MODE == 0) {
        #pragma unroll
        for (int mt = 0; mt < 2; mt++) {
            #pragma unroll
            for (int nt = 0; nt < NT; nt++) {
                int r0 = rowBase + wm*32 + mt*16 + (lane >> 2);
                int c0 = colBase + wn*(8*NT) + nt*8 + (lane & 3)*2;
                if (c0 < N) {
                    *(float2*)&C[(size_t)r0*N + c0] =
                        make_float2(acc[mt][nt][0], acc[mt][nt][1]);
                    *(float2*)&C[(size_t)(r0+8)*N + c0] =
                        make_float2(acc[mt][nt][2], acc[mt][nt][3]);
                }
            }
        }
    } else {
        // transpose tile through smem, then coalesced along l with residual
        __syncthreads();
        float* tr = (float*)sm;              // [64 c][132]
        #pragma unroll
        for (int mt = 0; mt < 2; mt++) {
            #pragma unroll
            for (int nt = 0; nt < NT; nt++) {
                int r  = wm*32 + mt*16 + (lane >> 2);
                int cl = wn*32 + nt*8 + (lane & 3)*2;
                tr[ cl   *132 + r    ] = acc[mt][nt][0];
                tr[(cl+1)*132 + r    ] = acc[mt][nt][1];
                tr[ cl   *132 + r + 8] = acc[mt][nt][2];
                tr[(cl+1)*132 + r + 8] = acc[mt][nt][3];
            }
        }
        __syncthreads();
        int b0 = rowBase >> 11;
        int lbase = rowBase & 2047;
        for (int i = tid; i < 64*32; i += 256) {
            int cl = i >> 5, j = i & 31;
            float4 v = *(float4*)&tr[cl*132 + j*4];
            size_t o = (size_t)b0*DMODEL*SEQ + (size_t)(colBase + cl)*SEQ + lbase + j*4;
            float4 rr = *(const float4*)&resid[o];
            v.x += rr.x; v.y += rr.y; v.z += rr.z; v.w += rr.w;
            *(float4*)&C[o] = v;
        }
    }
}

// ---------------- 3) depthwise causal conv (width 4) + SiLU, float4 ----------
__global__ __launch_bounds__(256) void conv_silu_kernel(
    const float* __restrict__ cw, const float* __restrict__ cb)
{
    int idx = blockIdx.x*256 + threadIdx.x;   // < NTOK*DINNER/4
    int t  = idx >> 7;
    int d4 = idx & 127;
    int d  = d4 * 4;
    int l  = t & 2047;

    float4 w0 = *(const float4*)(cw + (size_t)d*4);
    float4 w1 = *(const float4*)(cw + (size_t)(d+1)*4);
    float4 w2 = *(const float4*)(cw + (size_t)(d+2)*4);
    float4 w3 = *(const float4*)(cw + (size_t)(d+3)*4);
    float4 acc = *(const float4*)(cb + d);

    float4 v[4];
    #pragma unroll
    for (int j = 0; j < 4; j++) {
        int ls = l - 3 + j;
        v[j] = (ls >= 0) ? *(const float4*)(g_xz + (size_t)(t-3+j)*1024 + d)
                         : make_float4(0.f,0.f,0.f,0.f);
    }
    acc.x += w0.x*v[0].x + w0.y*v[1].x + w0.z*v[2].x + w0.w*v[3].x;
    acc.y += w1.x*v[0].y + w1.y*v[1].y + w1.z*v[2].y + w1.w*v[3].y;
    acc.z += w2.x*v[0].z + w2.y*v[1].z + w2.z*v[2].z + w2.w*v[3].z;
    acc.w += w3.x*v[0].w + w3.y*v[1].w + w3.z*v[2].w + w3.w*v[3].w;

    acc.x = acc.x / (1.f + __expf(-acc.x));
    acc.y = acc.y / (1.f + __expf(-acc.y));
    acc.z = acc.z / (1.f + __expf(-acc.z));
    acc.w = acc.w / (1.f + __expf(-acc.w));
    *(float4*)(g_xc + (size_t)idx*4) = acc;
}

// ---------------- 5) delta = softplus(dt @ dt_proj_w^T + b) ----------------
__global__ __launch_bounds__(256) void dtproj_kernel(
    const float* __restrict__ W, const float* __restrict__ bias)
{
    int t0 = blockIdx.x * 16;
    int tid = threadIdx.x;
    int d = tid * 2;
    __shared__ float st[16][17];
    {
        int t = tid >> 4, r = tid & 15;
        st[t][r] = g_dbl[(t0 + t)*48 + r];
    }
    __syncthreads();

    const float4* w0 = (const float4*)(W + (size_t)d*16);
    const float4* w1 = (const float4*)(W + (size_t)(d+1)*16);
    float4 wa0 = w0[0], wa1 = w0[1], wa2 = w0[2], wa3 = w0[3];
    float4 wb0 = w1[0], wb1 = w1[1], wb2 = w1[2], wb3 = w1[3];
    float b0 = bias[d], b1 = bias[d+1];

    #pragma unroll 4
    for (int t = 0; t < 16; t++) {
        const float* s = st[t];
        float a0 = b0, a1 = b1;
        a0 = fmaf(s[0],wa0.x,a0); a0 = fmaf(s[1],wa0.y,a0); a0 = fmaf(s[2],wa0.z,a0); a0 = fmaf(s[3],wa0.w,a0);
        a0 = fmaf(s[4],wa1.x,a0); a0 = fmaf(s[5],wa1.y,a0); a0 = fmaf(s[6],wa1.z,a0); a0 = fmaf(s[7],wa1.w,a0);
        a0 = fmaf(s[8],wa2.x,a0); a0 = fmaf(s[9],wa2.y,a0); a0 = fmaf(s[10],wa2.z,a0); a0 = fmaf(s[11],wa2.w,a0);
        a0 = fmaf(s[12],wa3.x,a0); a0 = fmaf(s[13],wa3.y,a0); a0 = fmaf(s[14],wa3.z,a0); a0 = fmaf(s[15],wa3.w,a0);
        a1 = fmaf(s[0],wb0.x,a1); a1 = fmaf(s[1],wb0.y,a1); a1 = fmaf(s[2],wb0.z,a1); a1 = fmaf(s[3],wb0.w,a1);
        a1 = fmaf(s[4],wb1.x,a1); a1 = fmaf(s[5],wb1.y,a1); a1 = fmaf(s[6],wb1.z,a1); a1 = fmaf(s[7],wb1.w,a1);
        a1 = fmaf(s[8],wb2.x,a1); a1 = fmaf(s[9],wb2.y,a1); a1 = fmaf(s[10],wb2.z,a1); a1 = fmaf(s[11],wb2.w,a1);
        a1 = fmaf(s[12],wb3.x,a1); a1 = fmaf(s[13],wb3.y,a1); a1 = fmaf(s[14],wb3.z,a1); a1 = fmaf(s[15],wb3.w,a1);
        a0 = (a0 > 20.f) ? a0 : log1pf(__expf(a0));
        a1 = (a1 > 20.f) ? a1 : log1pf(__expf(a1));
        *(float2*)&g_delta[(size_t)(t0+t)*DINNER + d] = make_float2(a0, a1);
    }
}

// ---------------- 6) selective scan: shuffle reduce + register prefetch -------
__global__ __launch_bounds__(128) void scan_kernel(
    const float* __restrict__ A_log, const float* __restrict__ Dp)
{
    int b   = blockIdx.y;
    int d0  = blockIdx.x * 8;
    int tid = threadIdx.x;
    int dl  = tid >> 4, n = tid & 15;
    int d   = d0 + dl;

    float a = -expf(A_log[d*DSTATE + n]);
    float h = 0.f;
    float Dval = Dp[d0 + (tid & 7)];

    __shared__ float sdelta[32][8], sx[32][8], sB[32][16], sC[32][16], sy[32][9];

    float rd[2], rx[2], rz[2], rb[4], rc[4], cz[2];

    // prologue: load + stage chunk 0
    #pragma unroll
    for (int k = 0; k < 2; k++) {
        int i = tid + k*128, t = i >> 3, dd = i & 7;
        size_t gt = (size_t)(b*SEQ + t);
        rd[k] = g_delta[gt*DINNER + d0 + dd];
        rx[k] = g_xc  [gt*DINNER + d0 + dd];
        rz[k] = g_xz  [gt*1024 + DINNER + d0 + dd];
    }
    #pragma unroll
    for (int k = 0; k < 4; k++) {
        int i = tid + k*128, t = i >> 4, nn = i & 15;
        int gt = b*SEQ + t;
        rb[k] = g_dbl[gt*48 + 16 + nn];
        rc[k] = g_dbl[gt*48 + 32 + nn];
    }
    #pragma unroll
    for (int k = 0; k < 2; k++) {
        int i = tid + k*128, t = i >> 3, dd = i & 7;
        sdelta[t][dd] = rd[k]; sx[t][dd] = rx[k];
        cz[k] = rz[k];
    }
    #pragma unroll
    for (int k = 0; k < 4; k++) {
        int i = tid + k*128, t = i >> 4, nn = i & 15;
        sB[t][nn] = rb[k]; sC[t][nn] = rc[k];
    }
    __syncthreads();

    for (int ch = 0; ch < 64; ch++) {
        bool more = (ch + 1) < 64;
        int l0n = (ch + 1) * 32;
        if (more) {
            #pragma unroll
            for (int k = 0; k < 2; k++) {
                int i = tid + k*128, t = i >> 3, dd = i & 7;
                size_t gt = (size_t)(b*SEQ + l0n + t);
                rd[k] = g_delta[gt*DINNER + d0 + dd];
                rx[k] = g_xc  [gt*DINNER + d0 + dd];
                rz[k] = g_xz  [gt*1024 + DINNER + d0 + dd];
            }
            #pragma unroll
            for (int k = 0; k < 4; k++) {
                int i = tid + k*128, t = i >> 4, nn = i & 15;
                int gt = b*SEQ + l0n + t;
                rb[k] = g_dbl[gt*48 + 16 + nn];
                rc[k] = g_dbl[gt*48 + 32 + nn];
            }
        }
        // recurrence + cross-n butterfly reduce (off h-chain)
        #pragma unroll
        for (int t = 0; t < 32; t++) {
            float dlt = sdelta[t][dl];
            float dA  = __expf(dlt * a);
            float dbx = dlt * sB[t][n] * sx[t][dl];
            h = fmaf(dA, h, dbx);
            float v = h * sC[t][n];
            v += __shfl_xor_sync(0xffffffffu, v, 8);
            v += __shfl_xor_sync(0xffffffffu, v, 4);
            v += __shfl_xor_sync(0xffffffffu, v, 2);
            v += __shfl_xor_sync(0xffffffffu, v, 1);
            if (n == 0) sy[t][dl] = v;
        }
        __syncthreads();
        // finalize current chunk (reads sy, sx, cz)
        #pragma unroll
        for (int k = 0; k < 2; k++) {
            int i = tid + k*128, t = i >> 3, dd = i & 7;
            size_t gt = (size_t)(b*SEQ + ch*32 + t);
            float yv = sy[t][dd] + sx[t][dd] * Dval;
            float zv = cz[k];
            yv *= zv / (1.f + __expf(-zv));
            g_yact[gt*DINNER + d0 + dd] = yv;
        }
        __syncthreads();
        if (more) {
            #pragma unroll
            for (int k = 0; k < 2; k++) {
                int i = tid + k*128, t = i >> 3, dd = i & 7;
                sdelta[t][dd] = rd[k]; sx[t][dd] = rx[k];
                cz[k] = rz[k];
            }
            #pragma unroll
            for (int k = 0; k < 4; k++) {
                int i = tid + k*128, t = i >> 4, nn = i & 15;
                sB[t][nn] = rb[k]; sC[t][nn] = rc[k];
            }
            __syncthreads();
        }
    }
}

// ---------------- launch ----------------
extern "C" void kernel_launch(void* const* d_in, const int* in_sizes, int n_in,
                              void* d_out, int out_size)
{
    const float* x          = (const float*)d_in[0];
    const float* norm_w     = (const float*)d_in[1];
    const float* in_proj_w  = (const float*)d_in[2];
    const float* conv_w     = (const float*)d_in[3];
    const float* conv_b     = (const float*)d_in[4];
    const float* x_proj_w   = (const float*)d_in[5];
    const float* dt_proj_w  = (const float*)d_in[6];
    const float* dt_proj_b  = (const float*)d_in[7];
    const float* A_log      = (const float*)d_in[8];
    const float* Dp         = (const float*)d_in[9];
    const float* out_proj_w = (const float*)d_in[10];
    float* out = (float*)d_out;
    (void)in_sizes; (void)n_in; (void)out_size;

    float *hn, *xz, *xc, *dbl, *yact;
    cudaGetSymbolAddress((void**)&hn,   g_hn);
    cudaGetSymbolAddress((void**)&xz,   g_xz);
    cudaGetSymbolAddress((void**)&xc,   g_xc);
    cudaGetSymbolAddress((void**)&dbl,  g_dbl);
    cudaGetSymbolAddress((void**)&yact, g_yact);

    // 1) rmsnorm
    rmsnorm_kernel<<<NTOK/32, 256>>>(x, norm_w);
    // 2) xz = hn @ in_proj_w^T           (4096 x 1024 x 256)
    mma_tn<0,128><<<dim3(32, 16), 256>>>(hn, in_proj_w, xz, NTOK, 2*DINNER, DMODEL, nullptr);
    // 3) xc = silu(causal_conv(xin))
    conv_silu_kernel<<<NTOK*DINNER/4/256, 256>>>(conv_w, conv_b);
    // 4) dbl = xc @ x_proj_w^T           (4096 x 48 x 512), thin tiles -> 128 blocks
    mma_tn<0,32><<<dim3(128, 1), 256>>>(xc, x_proj_w, dbl, NTOK, 48, DINNER, nullptr);
    // 5) delta = softplus(dt @ dt_proj_w^T + b)
    dtproj_kernel<<<NTOK/16, 256>>>(dt_proj_w, dt_proj_b);
    // 6) selective scan + gate
    scan_kernel<<<dim3(DINNER/8, BATCH), 128>>>(A_log, Dp);
    // 7) out = yact @ out_proj_w^T + residual, transposed to (B,C,1,L)
    mma_tn<1,128><<<dim3(32, 4), 256>>>(yact, out_proj_w, out, NTOK, DMODEL, DINNER, x);
}

// round 4
// speedup vs baseline: 1.1805x; 1.1805x over previous
#include <cuda_runtime.h>
#include <math.h>

#define BATCH  2
#define SEQ    2048
#define DMODEL 256
#define DINNER 512
#define DSTATE 16
#define NTOK   (BATCH*SEQ)   // 4096

// ---------------- scratch ----------------
__device__ float g_hn[NTOK*DMODEL];
__device__ float g_xz[NTOK*2*DINNER];
__device__ float g_xc[NTOK*DINNER];
__device__ float g_dbl[NTOK*48];
__device__ float g_delta[NTOK*DINNER];
__device__ float g_yact[NTOK*DINNER];

// ---------------- 1) RMSNorm: coalesced transposed reads + smem transpose ----
__global__ __launch_bounds__(256) void rmsnorm_kernel(
    const float* __restrict__ x, const float* __restrict__ nw)
{
    int l0 = blockIdx.x * 32;
    int b  = l0 >> 11;
    int lb = l0 & 2047;
    int w    = threadIdx.x >> 5;
    int lane = threadIdx.x & 31;

    __shared__ float st[256*33];
    __shared__ float ssum[32][9];
    __shared__ float rs[32];

    const float* xb = x + (size_t)b * DMODEL * SEQ + lb + lane;

    float vals[32];
    float ss = 0.f;
    #pragma unroll
    for (int ci = 0; ci < 32; ci++) {
        int c = ci*8 + w;
        float v = xb[(size_t)c * SEQ];
        vals[ci] = v;
        ss += v*v;
    }
    ssum[lane][w] = ss;
    __syncthreads();
    if (threadIdx.x < 32) {
        float tot = 0.f;
        #pragma unroll
        for (int j = 0; j < 8; j++) tot += ssum[threadIdx.x][j];
        rs[threadIdx.x] = rsqrtf(tot * (1.0f/DMODEL) + 1e-5f);
    }
    #pragma unroll
    for (int ci = 0; ci < 32; ci++)
        st[(ci*8 + w)*33 + lane] = vals[ci];
    __syncthreads();

    #pragma unroll
    for (int p = 0; p < 4; p++) {
        int t = (threadIdx.x >> 5) + p*8;
        float r = rs[t];
        float* orow = g_hn + (size_t)(l0 + t)*DMODEL;
        #pragma unroll
        for (int j = 0; j < 8; j++) {
            int c = lane + j*32;
            orow[c] = st[c*33 + t] * r * nw[c];
        }
    }
}

// ---------------- big GEMMs: cp.async double-buffered tf32 MMA ----------------
// C = A(MxK) * B(NxK)^T, tile 128x64x32, 8 warps (4m x 2n), warp tile 32x32.
// MODE 0: row-major store. MODE 1: out_proj epilogue (smem transpose + residual).
#define STG ((128+64)*36)

__device__ __forceinline__ void cpa16(unsigned dst, const float* src) {
    asm volatile("cp.async.ca.shared.global [%0], [%1], 16;\n" :: "r"(dst), "l"(src));
}

template<int MODE>
__global__ __launch_bounds__(256) void mma_pipe(
    const float* __restrict__ A, const float* __restrict__ Bw,
    float* __restrict__ C, int K, int N, const float* __restrict__ resid)
{
    extern __shared__ __align__(16) unsigned sm[];
    int tid  = threadIdx.x;
    int lane = tid & 31, w = tid >> 5;
    int wm = w & 3, wn = w >> 2;
    int rowBase = blockIdx.x * 128;
    int colBase = blockIdx.y * 64;
    int lr = tid >> 3, lc = (tid & 7) * 4;

    const float* Ag = A  + (size_t)(rowBase + lr)*K + lc;
    const float* Bg = Bw + (size_t)(colBase + lr)*K + lc;

    float acc[2][4][4];
    #pragma unroll
    for (int mt = 0; mt < 2; mt++)
        #pragma unroll
        for (int nt = 0; nt < 4; nt++)
            #pragma unroll
            for (int q = 0; q < 4; q++) acc[mt][nt][q] = 0.f;

    unsigned sbase = (unsigned)__cvta_generic_to_shared(sm);

    auto issue = [&](int kt, int buf) {
        unsigned ab = sbase + (unsigned)(buf*STG)*4u;
        #pragma unroll
        for (int i = 0; i < 4; i++)
            cpa16(ab + (unsigned)((lr + i*32)*36 + lc)*4u, Ag + kt + (size_t)i*32*K);
        unsigned bb = ab + 128u*36u*4u;
        #pragma unroll
        for (int i = 0; i < 2; i++)
            cpa16(bb + (unsigned)((lr + i*32)*36 + lc)*4u, Bg + kt + (size_t)i*32*K);
        asm volatile("cp.async.commit_group;\n");
    };

    int CH = K >> 5;
    issue(0, 0);

    for (int c = 0; c < CH; c++) {
        if (c + 1 < CH) {
            issue((c+1)*32, (c+1)&1);
            asm volatile("cp.async.wait_group 1;\n");
        } else {
            asm volatile("cp.async.wait_group 0;\n");
        }
        __syncthreads();

        unsigned (*As)[36] = (unsigned(*)[36])(sm + (c&1)*STG);
        unsigned (*Bs)[36] = (unsigned(*)[36])(sm + (c&1)*STG + 128*36);

        #pragma unroll
        for (int kk = 0; kk < 32; kk += 8) {
            unsigned a[2][4], bf[4][2];
            #pragma unroll
            for (int mt = 0; mt < 2; mt++) {
                int r = wm*32 + mt*16 + (lane >> 2);
                int cc = kk + (lane & 3);
                a[mt][0] = As[r  ][cc  ];
                a[mt][1] = As[r+8][cc  ];
                a[mt][2] = As[r  ][cc+4];
                a[mt][3] = As[r+8][cc+4];
            }
            #pragma unroll
            for (int nt = 0; nt < 4; nt++) {
                int nb = wn*32 + nt*8 + (lane >> 2);
                int cc = kk + (lane & 3);
                bf[nt][0] = Bs[nb][cc];
                bf[nt][1] = Bs[nb][cc+4];
            }
            #pragma unroll
            for (int mt = 0; mt < 2; mt++)
                #pragma unroll
                for (int nt = 0; nt < 4; nt++)
                    asm volatile(
                        "mma.sync.aligned.m16n8k8.row.col.f32.tf32.tf32.f32 "
                        "{%0,%1,%2,%3}, {%4,%5,%6,%7}, {%8,%9}, {%0,%1,%2,%3};"
                        : "+f"(acc[mt][nt][0]), "+f"(acc[mt][nt][1]),
                          "+f"(acc[mt][nt][2]), "+f"(acc[mt][nt][3])
                        : "r"(a[mt][0]), "r"(a[mt][1]), "r"(a[mt][2]), "r"(a[mt][3]),
                          "r"(bf[nt][0]), "r"(bf[nt][1]));
        }
        __syncthreads();
    }

    if (MODE == 0) {
        #pragma unroll
        for (int mt = 0; mt < 2; mt++) {
            #pragma unroll
            for (int nt = 0; nt < 4; nt++) {
                int r0 = rowBase + wm*32 + mt*16 + (lane >> 2);
                int c0 = colBase + wn*32 + nt*8 + (lane & 3)*2;
                *(float2*)&C[(size_t)r0*N + c0] =
                    make_float2(acc[mt][nt][0], acc[mt][nt][1]);
                *(float2*)&C[(size_t)(r0+8)*N + c0] =
                    make_float2(acc[mt][nt][2], acc[mt][nt][3]);
            }
        }
    } else {
        float* tr = (float*)sm;              // [64 c][132]
        #pragma unroll
        for (int mt = 0; mt < 2; mt++) {
            #pragma unroll
            for (int nt = 0; nt < 4; nt++) {
                int r  = wm*32 + mt*16 + (lane >> 2);
                int cl = wn*32 + nt*8 + (lane & 3)*2;
                tr[ cl   *132 + r    ] = acc[mt][nt][0];
                tr[(cl+1)*132 + r    ] = acc[mt][nt][1];
                tr[ cl   *132 + r + 8] = acc[mt][nt][2];
                tr[(cl+1)*132 + r + 8] = acc[mt][nt][3];
            }
        }
        __syncthreads();
        int b0 = rowBase >> 11;
        int lbase = rowBase & 2047;
        for (int i = tid; i < 64*32; i += 256) {
            int cl = i >> 5, j = i & 31;
            float4 v = *(float4*)&tr[cl*132 + j*4];
            size_t o = (size_t)b0*DMODEL*SEQ + (size_t)(colBase + cl)*SEQ + lbase + j*4;
            float4 rr = *(const float4*)&resid[o];
            v.x += rr.x; v.y += rr.y; v.z += rr.z; v.w += rr.w;
            *(float4*)&C[o] = v;
        }
    }
}

// ---------------- x_proj fused with conv+SiLU ----------------
// Block = 32 tokens, K loop over all 512 d. A-tile staging computes
// xc = silu(conv(xz)) on the fly, writes g_xc, feeds tf32 MMA vs x_proj_w.
__global__ __launch_bounds__(256) void xproj_conv_kernel(
    const float* __restrict__ Bw,      // x_proj_w [48][512]
    const float* __restrict__ cw, const float* __restrict__ cb)
{
    __shared__ unsigned As[32][36];
    __shared__ unsigned Bs[64][36];
    int tid = threadIdx.x, lane = tid & 31, w = tid >> 5;
    int rowBase = blockIdx.x * 32;
    int l0 = rowBase & 2047;

    float acc[2][4];
    #pragma unroll
    for (int mt = 0; mt < 2; mt++)
        #pragma unroll
        for (int q = 0; q < 4; q++) acc[mt][q] = 0.f;

    int tA   = tid >> 3;         // token 0..31
    int dOff = (tid & 7) * 4;    // d offset in chunk
    int gt   = rowBase + tA;
    int lrB  = tid >> 3;
    int lcB  = (tid & 7) * 4;

    for (int kc = 0; kc < DINNER; kc += 32) {
        // ---- A: conv + silu on xz, store to g_xc and smem ----
        int d = kc + dOff;
        float4 v[4];
        #pragma unroll
        for (int j = 0; j < 4; j++) {
            int ls = l0 + tA - 3 + j;
            v[j] = (ls >= 0) ? *(const float4*)(g_xz + (size_t)(gt-3+j)*1024 + d)
                             : make_float4(0.f,0.f,0.f,0.f);
        }
        float4 w0 = *(const float4*)(cw + (size_t)d*4);
        float4 w1 = *(const float4*)(cw + (size_t)(d+1)*4);
        float4 w2 = *(const float4*)(cw + (size_t)(d+2)*4);
        float4 w3 = *(const float4*)(cw + (size_t)(d+3)*4);
        float4 a4 = *(const float4*)(cb + d);
        a4.x += w0.x*v[0].x + w0.y*v[1].x + w0.z*v[2].x + w0.w*v[3].x;
        a4.y += w1.x*v[0].y + w1.y*v[1].y + w1.z*v[2].y + w1.w*v[3].y;
        a4.z += w2.x*v[0].z + w2.y*v[1].z + w2.z*v[2].z + w2.w*v[3].z;
        a4.w += w3.x*v[0].w + w3.y*v[1].w + w3.z*v[2].w + w3.w*v[3].w;
        a4.x = a4.x / (1.f + __expf(-a4.x));
        a4.y = a4.y / (1.f + __expf(-a4.y));
        a4.z = a4.z / (1.f + __expf(-a4.z));
        a4.w = a4.w / (1.f + __expf(-a4.w));
        *(float4*)(g_xc + (size_t)gt*DINNER + d) = a4;
        *(uint4*)&As[tA][dOff] = *(uint4*)&a4;

        // ---- B: x_proj_w rows (guard N=48) ----
        #pragma unroll
        for (int i = 0; i < 2; i++) {
            int bn = lrB + i*32;
            float4 bv = (bn < 48) ? *(const float4*)(Bw + (size_t)bn*DINNER + kc + lcB)
                                  : make_float4(0.f,0.f,0.f,0.f);
            *(uint4*)&Bs[bn][lcB] = *(uint4*)&bv;
        }
        __syncthreads();

        #pragma unroll
        for (int kk = 0; kk < 32; kk += 8) {
            unsigned a[2][4], bf[2];
            #pragma unroll
            for (int mt = 0; mt < 2; mt++) {
                int r = mt*16 + (lane >> 2);
                int cc = kk + (lane & 3);
                a[mt][0] = As[r  ][cc  ];
                a[mt][1] = As[r+8][cc  ];
                a[mt][2] = As[r  ][cc+4];
                a[mt][3] = As[r+8][cc+4];
            }
            {
                int nb = w*8 + (lane >> 2);
                int cc = kk + (lane & 3);
                bf[0] = Bs[nb][cc];
                bf[1] = Bs[nb][cc+4];
            }
            #pragma unroll
            for (int mt = 0; mt < 2; mt++)
                asm volatile(
                    "mma.sync.aligned.m16n8k8.row.col.f32.tf32.tf32.f32 "
                    "{%0,%1,%2,%3}, {%4,%5,%6,%7}, {%8,%9}, {%0,%1,%2,%3};"
                    : "+f"(acc[mt][0]), "+f"(acc[mt][1]),
                      "+f"(acc[mt][2]), "+f"(acc[mt][3])
                    : "r"(a[mt][0]), "r"(a[mt][1]), "r"(a[mt][2]), "r"(a[mt][3]),
                      "r"(bf[0]), "r"(bf[1]));
        }
        __syncthreads();
    }

    #pragma unroll
    for (int mt = 0; mt < 2; mt++) {
        int r0 = rowBase + mt*16 + (lane >> 2);
        int c0 = w*8 + (lane & 3)*2;
        if (c0 < 48) {
            *(float2*)&g_dbl[(size_t)r0*48 + c0] = make_float2(acc[mt][0], acc[mt][1]);
            *(float2*)&g_dbl[(size_t)(r0+8)*48 + c0] = make_float2(acc[mt][2], acc[mt][3]);
        }
    }
}

// ---------------- delta = softplus(dt @ dt_proj_w^T + b) ----------------
__global__ __launch_bounds__(256) void dtproj_kernel(
    const float* __restrict__ W, const float* __restrict__ bias)
{
    int t0 = blockIdx.x * 16;
    int tid = threadIdx.x;
    int d = tid * 2;
    __shared__ float st[16][17];
    {
        int t = tid >> 4, r = tid & 15;
        st[t][r] = g_dbl[(t0 + t)*48 + r];
    }
    __syncthreads();

    const float4* w0 = (const float4*)(W + (size_t)d*16);
    const float4* w1 = (const float4*)(W + (size_t)(d+1)*16);
    float4 wa0 = w0[0], wa1 = w0[1], wa2 = w0[2], wa3 = w0[3];
    float4 wb0 = w1[0], wb1 = w1[1], wb2 = w1[2], wb3 = w1[3];
    float b0 = bias[d], b1 = bias[d+1];

    #pragma unroll 4
    for (int t = 0; t < 16; t++) {
        const float* s = st[t];
        float a0 = b0, a1 = b1;
        a0 = fmaf(s[0],wa0.x,a0); a0 = fmaf(s[1],wa0.y,a0); a0 = fmaf(s[2],wa0.z,a0); a0 = fmaf(s[3],wa0.w,a0);
        a0 = fmaf(s[4],wa1.x,a0); a0 = fmaf(s[5],wa1.y,a0); a0 = fmaf(s[6],wa1.z,a0); a0 = fmaf(s[7],wa1.w,a0);
        a0 = fmaf(s[8],wa2.x,a0); a0 = fmaf(s[9],wa2.y,a0); a0 = fmaf(s[10],wa2.z,a0); a0 = fmaf(s[11],wa2.w,a0);
        a0 = fmaf(s[12],wa3.x,a0); a0 = fmaf(s[13],wa3.y,a0); a0 = fmaf(s[14],wa3.z,a0); a0 = fmaf(s[15],wa3.w,a0);
        a1 = fmaf(s[0],wb0.x,a1); a1 = fmaf(s[1],wb0.y,a1); a1 = fmaf(s[2],wb0.z,a1); a1 = fmaf(s[3],wb0.w,a1);
        a1 = fmaf(s[4],wb1.x,a1); a1 = fmaf(s[5],wb1.y,a1); a1 = fmaf(s[6],wb1.z,a1); a1 = fmaf(s[7],wb1.w,a1);
        a1 = fmaf(s[8],wb2.x,a1); a1 = fmaf(s[9],wb2.y,a1); a1 = fmaf(s[10],wb2.z,a1); a1 = fmaf(s[11],wb2.w,a1);
        a1 = fmaf(s[12],wb3.x,a1); a1 = fmaf(s[13],wb3.y,a1); a1 = fmaf(s[14],wb3.z,a1); a1 = fmaf(s[15],wb3.w,a1);
        a0 = (a0 > 20.f) ? a0 : log1pf(__expf(a0));
        a1 = (a1 > 20.f) ? a1 : log1pf(__expf(a1));
        *(float2*)&g_delta[(size_t)(t0+t)*DINNER + d] = make_float2(a0, a1);
    }
}

// ---------------- selective scan (R2 version: smem-staged reduce) -----------
__global__ __launch_bounds__(128) void scan_kernel(
    const float* __restrict__ A_log, const float* __restrict__ Dp)
{
    int b   = blockIdx.y;
    int d0  = blockIdx.x * 8;
    int tid = threadIdx.x;
    int dl  = tid >> 4, n = tid & 15;
    int d   = d0 + dl;

    float a = -expf(A_log[d*DSTATE + n]);
    float h = 0.f;

    __shared__ float sdelta[32][8], sx[32][8], sB[32][16], sC[32][16];
    __shared__ float shc[32][128];

    for (int l0 = 0; l0 < SEQ; l0 += 32) {
        #pragma unroll
        for (int i = tid; i < 256; i += 128) {
            int t = i >> 3, dd = i & 7;
            int gt = b*SEQ + l0 + t;
            sdelta[t][dd] = g_delta[(size_t)gt*DINNER + d0 + dd];
            sx[t][dd]     = g_xc  [(size_t)gt*DINNER + d0 + dd];
        }
        #pragma unroll
        for (int i = tid; i < 512; i += 128) {
            int t = i >> 4, nn = i & 15;
            int gt = b*SEQ + l0 + t;
            sB[t][nn] = g_dbl[gt*48 + 16 + nn];
            sC[t][nn] = g_dbl[gt*48 + 32 + nn];
        }
        __syncthreads();

        #pragma unroll
        for (int t = 0; t < 32; t++) {
            float dlt = sdelta[t][dl];
            float dA  = __expf(dlt * a);
            float dbx = dlt * sB[t][n] * sx[t][dl];
            h = fmaf(dA, h, dbx);
            shc[t][tid] = h * sC[t][n];
        }
        __syncthreads();

        #pragma unroll
        for (int i = tid; i < 256; i += 128) {
            int t = i >> 3, dd = i & 7;
            float s = 0.f;
            #pragma unroll
            for (int q = 0; q < 16; q++) s += shc[t][dd*16 + q];
            int d2 = d0 + dd;
            int gt = b*SEQ + l0 + t;
            float yv = fmaf(sx[t][dd], Dp[d2], s);
            float zv = g_xz[(size_t)gt*1024 + DINNER + d2];
            yv *= zv / (1.f + __expf(-zv));
            g_yact[(size_t)gt*DINNER + d2] = yv;
        }
        __syncthreads();
    }
}

// ---------------- launch ----------------
extern "C" void kernel_launch(void* const* d_in, const int* in_sizes, int n_in,
                              void* d_out, int out_size)
{
    const float* x          = (const float*)d_in[0];
    const float* norm_w     = (const float*)d_in[1];
    const float* in_proj_w  = (const float*)d_in[2];
    const float* conv_w     = (const float*)d_in[3];
    const float* conv_b     = (const float*)d_in[4];
    const float* x_proj_w   = (const float*)d_in[5];
    const float* dt_proj_w  = (const float*)d_in[6];
    const float* dt_proj_b  = (const float*)d_in[7];
    const float* A_log      = (const float*)d_in[8];
    const float* Dp         = (const float*)d_in[9];
    const float* out_proj_w = (const float*)d_in[10];
    float* out = (float*)d_out;
    (void)in_sizes; (void)n_in; (void)out_size;

    float *hn, *xz, *yact;
    cudaGetSymbolAddress((void**)&hn,   g_hn);
    cudaGetSymbolAddress((void**)&xz,   g_xz);
    cudaGetSymbolAddress((void**)&yact, g_yact);

    const int SMEM = STG * 2 * 4;   // 55296 bytes
    cudaFuncSetAttribute(mma_pipe<0>, cudaFuncAttributeMaxDynamicSharedMemorySize, SMEM);
    cudaFuncSetAttribute(mma_pipe<1>, cudaFuncAttributeMaxDynamicSharedMemorySize, SMEM);

    // 1) rmsnorm
    rmsnorm_kernel<<<NTOK/32, 256>>>(x, norm_w);
    // 2) xz = hn @ in_proj_w^T           (4096 x 1024 x 256)
    mma_pipe<0><<<dim3(32, 16), 256, SMEM>>>(hn, in_proj_w, xz, DMODEL, 2*DINNER, nullptr);
    // 3+4) xc = silu(conv(xin)); dbl = xc @ x_proj_w^T  (fused)
    xproj_conv_kernel<<<NTOK/32, 256>>>(x_proj_w, conv_w, conv_b);
    // 5) delta = softplus(dt @ dt_proj_w^T + b)
    dtproj_kernel<<<NTOK/16, 256>>>(dt_proj_w, dt_proj_b);
    // 6) selective scan + gate
    scan_kernel<<<dim3(DINNER/8, BATCH), 128>>>(A_log, Dp);
    // 7) out = yact @ out_proj_w^T + residual, transposed
    mma_pipe<1><<<dim3(32, 4), 256, SMEM>>>(yact, out_proj_w, out, DINNER, DMODEL, x);
}

// round 5
// speedup vs baseline: 1.4706x; 1.2457x over previous
#include <cuda_runtime.h>
#include <cuda_fp16.h>
#include <math.h>

#define BATCH  2
#define SEQ    2048
#define DMODEL 256
#define DINNER 512
#define DSTATE 16
#define NTOK   (BATCH*SEQ)   // 4096

// ---------------- scratch ----------------
__device__ __half g_hn_h[NTOK*DMODEL];      // rmsnorm output (fp16)
__device__ float  g_xz[NTOK*2*DINNER];      // in_proj output (fp32)
__device__ float  g_xc[NTOK*DINNER];        // conv+silu output (fp32)
__device__ float  g_dbl[NTOK*48];           // x_proj output (dt|B|C)
__device__ __half g_yact_h[NTOK*DINNER];    // y * silu(z) (fp16)
__device__ __half g_win_h[2*DINNER*DMODEL]; // in_proj_w fp16
__device__ __half g_wout_h[DMODEL*DINNER];  // out_proj_w fp16

__device__ __forceinline__ void cpa16(unsigned dst, const void* src) {
    asm volatile("cp.async.ca.shared.global [%0], [%1], 16;\n" :: "r"(dst), "l"(src));
}

// ---------------- 0) weight conversion fp32 -> fp16 ----------------
__global__ __launch_bounds__(256) void cvt_weights(
    const float* __restrict__ win, const float* __restrict__ wout)
{
    int i = blockIdx.x*256 + threadIdx.x;
    if (i < 2*DINNER*DMODEL) g_win_h[i] = __float2half(win[i]);
    if (i < DMODEL*DINNER)   g_wout_h[i] = __float2half(wout[i]);
}

// ---------------- 1) RMSNorm: coalesced reads, writes fp16 ----------------
__global__ __launch_bounds__(256) void rmsnorm_kernel(
    const float* __restrict__ x, const float* __restrict__ nw)
{
    int l0 = blockIdx.x * 32;
    int b  = l0 >> 11;
    int lb = l0 & 2047;
    int w    = threadIdx.x >> 5;
    int lane = threadIdx.x & 31;

    __shared__ float st[256*33];
    __shared__ float ssum[32][9];
    __shared__ float rs[32];

    const float* xb = x + (size_t)b * DMODEL * SEQ + lb + lane;

    float vals[32];
    float ss = 0.f;
    #pragma unroll
    for (int ci = 0; ci < 32; ci++) {
        int c = ci*8 + w;
        float v = xb[(size_t)c * SEQ];
        vals[ci] = v;
        ss += v*v;
    }
    ssum[lane][w] = ss;
    __syncthreads();
    if (threadIdx.x < 32) {
        float tot = 0.f;
        #pragma unroll
        for (int j = 0; j < 8; j++) tot += ssum[threadIdx.x][j];
        rs[threadIdx.x] = rsqrtf(tot * (1.0f/DMODEL) + 1e-5f);
    }
    #pragma unroll
    for (int ci = 0; ci < 32; ci++)
        st[(ci*8 + w)*33 + lane] = vals[ci];
    __syncthreads();

    #pragma unroll
    for (int p = 0; p < 4; p++) {
        int t = (threadIdx.x >> 5) + p*8;
        float r = rs[t];
        __half* orow = g_hn_h + (size_t)(l0 + t)*DMODEL;
        #pragma unroll
        for (int j = 0; j < 8; j++) {
            int c = lane + j*32;
            orow[c] = __float2half(st[c*33 + t] * r * nw[c]);
        }
    }
}

// ---------------- fp16 tensor-core GEMM: C = A(MxK) * B(NxK)^T --------------
// m16n8k16, tile 128x64x32, 8 warps (4m x 2n), cp.async double buffered.
// smem rows padded to 40 halfs (80B = 20 words) -> conflict-free frag loads.
// MODE 0: fp32 row-major store. MODE 1: out_proj epilogue (transpose+residual).
#define HBUF 3840   // words per buffer (A 128*20 + B 64*20)

template<int MODE>
__global__ __launch_bounds__(256) void mma_pipe_h(
    const __half* __restrict__ A, const __half* __restrict__ Bw,
    float* __restrict__ C, int K, int N, const float* __restrict__ resid)
{
    extern __shared__ __align__(16) unsigned sm[];
    int tid  = threadIdx.x;
    int lane = tid & 31, w = tid >> 5;
    int wm = w & 3, wn = w >> 2;
    int rowBase = blockIdx.x * 128;
    int colBase = blockIdx.y * 64;

    int arow = tid >> 1, aseg = tid & 1;     // A: 2 threads/row, 2x16B each
    int brow = tid >> 2, bseg = tid & 3;     // B: 4 threads/row, 1x16B each
    const __half* Ag = A  + (size_t)(rowBase + arow)*K + aseg*16;
    const __half* Bg = Bw + (size_t)(colBase + brow)*K + bseg*8;

    float acc[2][4][4];
    #pragma unroll
    for (int mt = 0; mt < 2; mt++)
        #pragma unroll
        for (int nt = 0; nt < 4; nt++)
            #pragma unroll
            for (int q = 0; q < 4; q++) acc[mt][nt][q] = 0.f;

    unsigned sbase = (unsigned)__cvta_generic_to_shared(sm);

    auto issue = [&](int kt, int buf) {
        unsigned ab = sbase + (unsigned)buf*15360u;
        cpa16(ab + (unsigned)(arow*80 + aseg*32),      Ag + kt);
        cpa16(ab + (unsigned)(arow*80 + aseg*32 + 16), Ag + kt + 8);
        cpa16(ab + 10240u + (unsigned)(brow*80 + bseg*16), Bg + kt);
        asm volatile("cp.async.commit_group;\n");
    };

    int CH = K >> 5;
    issue(0, 0);

    for (int c = 0; c < CH; c++) {
        if (c + 1 < CH) {
            issue((c+1)*32, (c+1)&1);
            asm volatile("cp.async.wait_group 1;\n");
        } else {
            asm volatile("cp.async.wait_group 0;\n");
        }
        __syncthreads();

        const unsigned* Asw = sm + (c&1)*HBUF;
        const unsigned* Bsw = Asw + 2560;

        #pragma unroll
        for (int ks = 0; ks < 2; ks++) {
            int kw = ks*8;
            unsigned a[2][4], bq[4][2];
            #pragma unroll
            for (int mt = 0; mt < 2; mt++) {
                int r0 = wm*32 + mt*16 + (lane >> 2);
                int bi = r0*20 + kw + (lane & 3);
                a[mt][0] = Asw[bi];
                a[mt][1] = Asw[bi + 160];
                a[mt][2] = Asw[bi + 4];
                a[mt][3] = Asw[bi + 164];
            }
            #pragma unroll
            for (int nt = 0; nt < 4; nt++) {
                int n0 = wn*32 + nt*8 + (lane >> 2);
                int bb = n0*20 + kw + (lane & 3);
                bq[nt][0] = Bsw[bb];
                bq[nt][1] = Bsw[bb + 4];
            }
            #pragma unroll
            for (int mt = 0; mt < 2; mt++)
                #pragma unroll
                for (int nt = 0; nt < 4; nt++)
                    asm volatile(
                        "mma.sync.aligned.m16n8k16.row.col.f32.f16.f16.f32 "
                        "{%0,%1,%2,%3}, {%4,%5,%6,%7}, {%8,%9}, {%0,%1,%2,%3};"
                        : "+f"(acc[mt][nt][0]), "+f"(acc[mt][nt][1]),
                          "+f"(acc[mt][nt][2]), "+f"(acc[mt][nt][3])
                        : "r"(a[mt][0]), "r"(a[mt][1]), "r"(a[mt][2]), "r"(a[mt][3]),
                          "r"(bq[nt][0]), "r"(bq[nt][1]));
        }
        __syncthreads();
    }

    if (MODE == 0) {
        #pragma unroll
        for (int mt = 0; mt < 2; mt++) {
            #pragma unroll
            for (int nt = 0; nt < 4; nt++) {
                int r0 = rowBase + wm*32 + mt*16 + (lane >> 2);
                int c0 = colBase + wn*32 + nt*8 + (lane & 3)*2;
                *(float2*)&C[(size_t)r0*N + c0] =
                    make_float2(acc[mt][nt][0], acc[mt][nt][1]);
                *(float2*)&C[(size_t)(r0+8)*N + c0] =
                    make_float2(acc[mt][nt][2], acc[mt][nt][3]);
            }
        }
    } else {
        float* tr = (float*)sm;              // [64 c][132]
        #pragma unroll
        for (int mt = 0; mt < 2; mt++) {
            #pragma unroll
            for (int nt = 0; nt < 4; nt++) {
                int r  = wm*32 + mt*16 + (lane >> 2);
                int cl = wn*32 + nt*8 + (lane & 3)*2;
                tr[ cl   *132 + r    ] = acc[mt][nt][0];
                tr[(cl+1)*132 + r    ] = acc[mt][nt][1];
                tr[ cl   *132 + r + 8] = acc[mt][nt][2];
                tr[(cl+1)*132 + r + 8] = acc[mt][nt][3];
            }
        }
        __syncthreads();
        int b0 = rowBase >> 11;
        int lbase = rowBase & 2047;
        for (int i = tid; i < 64*32; i += 256) {
            int cl = i >> 5, j = i & 31;
            float4 v = *(float4*)&tr[cl*132 + j*4];
            size_t o = (size_t)b0*DMODEL*SEQ + (size_t)(colBase + cl)*SEQ + lbase + j*4;
            float4 rr = *(const float4*)&resid[o];
            v.x += rr.x; v.y += rr.y; v.z += rr.z; v.w += rr.w;
            *(float4*)&C[o] = v;
        }
    }
}

// ---------------- x_proj fused with conv+SiLU (tf32) ----------------
__global__ __launch_bounds__(256) void xproj_conv_kernel(
    const float* __restrict__ Bw,      // x_proj_w [48][512]
    const float* __restrict__ cw, const float* __restrict__ cb)
{
    __shared__ unsigned As[32][36];
    __shared__ unsigned Bs[64][36];
    int tid = threadIdx.x, lane = tid & 31, w = tid >> 5;
    int rowBase = blockIdx.x * 32;
    int l0 = rowBase & 2047;

    float acc[2][4];
    #pragma unroll
    for (int mt = 0; mt < 2; mt++)
        #pragma unroll
        for (int q = 0; q < 4; q++) acc[mt][q] = 0.f;

    int tA   = tid >> 3;
    int dOff = (tid & 7) * 4;
    int gt   = rowBase + tA;
    int lrB  = tid >> 3;
    int lcB  = (tid & 7) * 4;

    for (int kc = 0; kc < DINNER; kc += 32) {
        int d = kc + dOff;
        float4 v[4];
        #pragma unroll
        for (int j = 0; j < 4; j++) {
            int ls = l0 + tA - 3 + j;
            v[j] = (ls >= 0) ? *(const float4*)(g_xz + (size_t)(gt-3+j)*1024 + d)
                             : make_float4(0.f,0.f,0.f,0.f);
        }
        float4 w0 = *(const float4*)(cw + (size_t)d*4);
        float4 w1 = *(const float4*)(cw + (size_t)(d+1)*4);
        float4 w2 = *(const float4*)(cw + (size_t)(d+2)*4);
        float4 w3 = *(const float4*)(cw + (size_t)(d+3)*4);
        float4 a4 = *(const float4*)(cb + d);
        a4.x += w0.x*v[0].x + w0.y*v[1].x + w0.z*v[2].x + w0.w*v[3].x;
        a4.y += w1.x*v[0].y + w1.y*v[1].y + w1.z*v[2].y + w1.w*v[3].y;
        a4.z += w2.x*v[0].z + w2.y*v[1].z + w2.z*v[2].z + w2.w*v[3].z;
        a4.w += w3.x*v[0].w + w3.y*v[1].w + w3.z*v[2].w + w3.w*v[3].w;
        a4.x = a4.x / (1.f + __expf(-a4.x));
        a4.y = a4.y / (1.f + __expf(-a4.y));
        a4.z = a4.z / (1.f + __expf(-a4.z));
        a4.w = a4.w / (1.f + __expf(-a4.w));
        *(float4*)(g_xc + (size_t)gt*DINNER + d) = a4;
        asm("cvt.rna.tf32.f32 %0, %1;" : "=r"(As[tA][dOff+0]) : "f"(a4.x));
        asm("cvt.rna.tf32.f32 %0, %1;" : "=r"(As[tA][dOff+1]) : "f"(a4.y));
        asm("cvt.rna.tf32.f32 %0, %1;" : "=r"(As[tA][dOff+2]) : "f"(a4.z));
        asm("cvt.rna.tf32.f32 %0, %1;" : "=r"(As[tA][dOff+3]) : "f"(a4.w));

        #pragma unroll
        for (int i = 0; i < 2; i++) {
            int bn = lrB + i*32;
            float4 bv = (bn < 48) ? *(const float4*)(Bw + (size_t)bn*DINNER + kc + lcB)
                                  : make_float4(0.f,0.f,0.f,0.f);
            asm("cvt.rna.tf32.f32 %0, %1;" : "=r"(Bs[bn][lcB+0]) : "f"(bv.x));
            asm("cvt.rna.tf32.f32 %0, %1;" : "=r"(Bs[bn][lcB+1]) : "f"(bv.y));
            asm("cvt.rna.tf32.f32 %0, %1;" : "=r"(Bs[bn][lcB+2]) : "f"(bv.z));
            asm("cvt.rna.tf32.f32 %0, %1;" : "=r"(Bs[bn][lcB+3]) : "f"(bv.w));
        }
        __syncthreads();

        #pragma unroll
        for (int kk = 0; kk < 32; kk += 8) {
            unsigned a[2][4], bf[2];
            #pragma unroll
            for (int mt = 0; mt < 2; mt++) {
                int r = mt*16 + (lane >> 2);
                int cc = kk + (lane & 3);
                a[mt][0] = As[r  ][cc  ];
                a[mt][1] = As[r+8][cc  ];
                a[mt][2] = As[r  ][cc+4];
                a[mt][3] = As[r+8][cc+4];
            }
            {
                int nb = w*8 + (lane >> 2);
                int cc = kk + (lane & 3);
                bf[0] = Bs[nb][cc];
                bf[1] = Bs[nb][cc+4];
            }
            #pragma unroll
            for (int mt = 0; mt < 2; mt++)
                asm volatile(
                    "mma.sync.aligned.m16n8k8.row.col.f32.tf32.tf32.f32 "
                    "{%0,%1,%2,%3}, {%4,%5,%6,%7}, {%8,%9}, {%0,%1,%2,%3};"
                    : "+f"(acc[mt][0]), "+f"(acc[mt][1]),
                      "+f"(acc[mt][2]), "+f"(acc[mt][3])
                    : "r"(a[mt][0]), "r"(a[mt][1]), "r"(a[mt][2]), "r"(a[mt][3]),
                      "r"(bf[0]), "r"(bf[1]));
        }
        __syncthreads();
    }

    #pragma unroll
    for (int mt = 0; mt < 2; mt++) {
        int r0 = rowBase + mt*16 + (lane >> 2);
        int c0 = w*8 + (lane & 3)*2;
        if (c0 < 48) {
            *(float2*)&g_dbl[(size_t)r0*48 + c0] = make_float2(acc[mt][0], acc[mt][1]);
            *(float2*)&g_dbl[(size_t)(r0+8)*48 + c0] = make_float2(acc[mt][2], acc[mt][3]);
        }
    }
}

// ---------------- selective scan: fused dt_proj + cp.async double buffer ----
__global__ __launch_bounds__(128) void scan_kernel(
    const float* __restrict__ A_log, const float* __restrict__ Dp,
    const float* __restrict__ dtW, const float* __restrict__ dtB)
{
    int b   = blockIdx.y;
    int d0  = blockIdx.x * 8;
    int tid = threadIdx.x;
    int dl  = tid >> 4, n = tid & 15;
    int d   = d0 + dl;

    float a = -expf(A_log[d*DSTATE + n]);
    float h = 0.f;
    float Dval = Dp[d0 + (tid & 7)];

    __shared__ float sdbl[2][32][52];    // raw dt|B|C rows (48 used, cp.async pad)
    __shared__ float sxc[2][32][8];
    __shared__ float sz[2][32][8];
    __shared__ float sdelta[32][8];
    __shared__ float shc[32][128];
    __shared__ float sW[128];
    __shared__ float sbias[8];

    sW[tid] = dtW[(size_t)(d0 + (tid >> 4))*16 + (tid & 15)];
    if (tid < 8) sbias[tid] = dtB[d0 + tid];

    unsigned adbl = (unsigned)__cvta_generic_to_shared(&sdbl[0][0][0]);
    unsigned axc  = (unsigned)__cvta_generic_to_shared(&sxc[0][0][0]);
    unsigned az   = (unsigned)__cvta_generic_to_shared(&sz[0][0][0]);

    auto issue = [&](int ch, int buf) {
        int base = b*SEQ + ch*32;
        #pragma unroll
        for (int k = 0; k < 3; k++) {
            int i = tid + k*128;
            int t = i / 12, s = i % 12;
            cpa16(adbl + (unsigned)((buf*32*52 + t*52 + s*4)*4),
                  g_dbl + (size_t)(base + t)*48 + s*4);
        }
        if (tid < 64) {
            int t = tid >> 1, hf = tid & 1;
            cpa16(axc + (unsigned)((buf*256 + t*8 + hf*4)*4),
                  g_xc + (size_t)(base + t)*DINNER + d0 + hf*4);
        } else {
            int i = tid - 64;
            int t = i >> 1, hf = i & 1;
            cpa16(az + (unsigned)((buf*256 + t*8 + hf*4)*4),
                  g_xz + (size_t)(base + t)*1024 + DINNER + d0 + hf*4);
        }
        asm volatile("cp.async.commit_group;\n");
    };

    issue(0, 0);

    for (int ch = 0; ch < 64; ch++) {
        if (ch + 1 < 64) {
            issue(ch + 1, (ch + 1) & 1);
            asm volatile("cp.async.wait_group 1;\n");
        } else {
            asm volatile("cp.async.wait_group 0;\n");
        }
        __syncthreads();
        int buf = ch & 1;

        // delta = softplus(dt . W + bias), 2 outputs per thread
        #pragma unroll
        for (int k = 0; k < 2; k++) {
            int i = tid + k*128;
            int t = i >> 3, dd = i & 7;
            float acc = sbias[dd];
            const float* row = sdbl[buf][t];
            const float* wv  = &sW[dd*16];
            #pragma unroll
            for (int r = 0; r < 16; r++) acc = fmaf(row[r], wv[r], acc);
            acc = (acc > 20.f) ? acc : log1pf(__expf(acc));
            sdelta[t][dd] = acc;
        }
        __syncthreads();

        // recurrence (h chain in registers)
        #pragma unroll
        for (int t = 0; t < 32; t++) {
            float dlt = sdelta[t][dl];
            float dA  = __expf(dlt * a);
            float dbx = dlt * sdbl[buf][t][16 + n] * sxc[buf][t][dl];
            h = fmaf(dA, h, dbx);
            shc[t][tid] = h * sdbl[buf][t][32 + n];
        }
        __syncthreads();

        // reduce over n + D skip + gate, store fp16
        #pragma unroll
        for (int k = 0; k < 2; k++) {
            int i = tid + k*128;
            int t = i >> 3, dd = i & 7;
            float s = 0.f;
            #pragma unroll
            for (int q = 0; q < 16; q++) s += shc[t][dd*16 + q];
            float yv = fmaf(sxc[buf][t][dd], Dval, s);
            float zv = sz[buf][t][dd];
            yv *= zv / (1.f + __expf(-zv));
            g_yact_h[(size_t)(b*SEQ + ch*32 + t)*DINNER + d0 + dd] = __float2half(yv);
        }
        __syncthreads();
    }
}

// ---------------- launch ----------------
extern "C" void kernel_launch(void* const* d_in, const int* in_sizes, int n_in,
                              void* d_out, int out_size)
{
    const float* x          = (const float*)d_in[0];
    const float* norm_w     = (const float*)d_in[1];
    const float* in_proj_w  = (const float*)d_in[2];
    const float* conv_w     = (const float*)d_in[3];
    const float* conv_b     = (const float*)d_in[4];
    const float* x_proj_w   = (const float*)d_in[5];
    const float* dt_proj_w  = (const float*)d_in[6];
    const float* dt_proj_b  = (const float*)d_in[7];
    const float* A_log      = (const float*)d_in[8];
    const float* Dp         = (const float*)d_in[9];
    const float* out_proj_w = (const float*)d_in[10];
    float* out = (float*)d_out;
    (void)in_sizes; (void)n_in; (void)out_size;

    __half *hn_h, *yact_h, *win_h, *wout_h;
    float *xz;
    cudaGetSymbolAddress((void**)&hn_h,   g_hn_h);
    cudaGetSymbolAddress((void**)&xz,     g_xz);
    cudaGetSymbolAddress((void**)&yact_h, g_yact_h);
    cudaGetSymbolAddress((void**)&win_h,  g_win_h);
    cudaGetSymbolAddress((void**)&wout_h, g_wout_h);

    const int SMEM = 34816;  // max(2*15360 pipeline, 33792 MODE1 transpose)
    cudaFuncSetAttribute(mma_pipe_h<0>, cudaFuncAttributeMaxDynamicSharedMemorySize, SMEM);
    cudaFuncSetAttribute(mma_pipe_h<1>, cudaFuncAttributeMaxDynamicSharedMemorySize, SMEM);

    // 0) weights -> fp16
    cvt_weights<<<(2*DINNER*DMODEL + 255)/256, 256>>>(in_proj_w, out_proj_w);
    // 1) rmsnorm (fp16 out)
    rmsnorm_kernel<<<NTOK/32, 256>>>(x, norm_w);
    // 2) xz = hn @ in_proj_w^T  (fp16 mma, 4096 x 1024 x 256)
    mma_pipe_h<0><<<dim3(32, 16), 256, SMEM>>>(hn_h, win_h, xz, DMODEL, 2*DINNER, nullptr);
    // 3+4) xc = silu(conv(xin)); dbl = xc @ x_proj_w^T (fused, tf32)
    xproj_conv_kernel<<<NTOK/32, 256>>>(x_proj_w, conv_w, conv_b);
    // 5+6) delta (fused dt_proj) + selective scan + gate (fp16 out)
    scan_kernel<<<dim3(DINNER/8, BATCH), 128>>>(A_log, Dp, dt_proj_w, dt_proj_b);
    // 7) out = yact @ out_proj_w^T + residual (fp16 mma, transposed store)
    mma_pipe_h<1><<<dim3(32, 4), 256, SMEM>>>(yact_h, wout_h, out, DINNER, DMODEL, x);
}

// round 6
// speedup vs baseline: 1.4829x; 1.0083x over previous
#include <cuda_runtime.h>
#include <cuda_fp16.h>
#include <math.h>

#define BATCH  2
#define SEQ    2048
#define DMODEL 256
#define DINNER 512
#define DSTATE 16
#define NTOK   (BATCH*SEQ)   // 4096

// ---------------- scratch ----------------
__device__ __half g_hn_h[NTOK*DMODEL];      // rmsnorm output (fp16)
__device__ float  g_xz[NTOK*2*DINNER];      // in_proj output (fp32)
__device__ float  g_xc[NTOK*DINNER];        // conv+silu output (fp32)
__device__ float  g_dbl[NTOK*48];           // x_proj output (dt|B|C)
__device__ __half g_yact_h[NTOK*DINNER];    // y * silu(z) (fp16)
__device__ __half g_win_h[2*DINNER*DMODEL]; // in_proj_w fp16
__device__ __half g_wout_h[DMODEL*DINNER];  // out_proj_w fp16
__device__ __half g_wxp_h[48*DINNER];       // x_proj_w fp16

__device__ __forceinline__ void cpa16(unsigned dst, const void* src) {
    asm volatile("cp.async.ca.shared.global [%0], [%1], 16;\n" :: "r"(dst), "l"(src));
}

// ---------------- 0) weight conversion fp32 -> fp16 ----------------
__global__ __launch_bounds__(256) void cvt_weights(
    const float* __restrict__ win, const float* __restrict__ wout,
    const float* __restrict__ wxp)
{
    int i = blockIdx.x*256 + threadIdx.x;
    if (i < 2*DINNER*DMODEL) g_win_h[i] = __float2half(win[i]);
    if (i < DMODEL*DINNER)   g_wout_h[i] = __float2half(wout[i]);
    if (i < 48*DINNER)       g_wxp_h[i] = __float2half(wxp[i]);
}

// ---------------- 1) RMSNorm: coalesced reads, writes fp16 ----------------
__global__ __launch_bounds__(256) void rmsnorm_kernel(
    const float* __restrict__ x, const float* __restrict__ nw)
{
    int l0 = blockIdx.x * 32;
    int b  = l0 >> 11;
    int lb = l0 & 2047;
    int w    = threadIdx.x >> 5;
    int lane = threadIdx.x & 31;

    __shared__ float st[256*33];
    __shared__ float ssum[32][9];
    __shared__ float rs[32];

    const float* xb = x + (size_t)b * DMODEL * SEQ + lb + lane;

    float vals[32];
    float ss = 0.f;
    #pragma unroll
    for (int ci = 0; ci < 32; ci++) {
        int c = ci*8 + w;
        float v = xb[(size_t)c * SEQ];
        vals[ci] = v;
        ss += v*v;
    }
    ssum[lane][w] = ss;
    __syncthreads();
    if (threadIdx.x < 32) {
        float tot = 0.f;
        #pragma unroll
        for (int j = 0; j < 8; j++) tot += ssum[threadIdx.x][j];
        rs[threadIdx.x] = rsqrtf(tot * (1.0f/DMODEL) + 1e-5f);
    }
    #pragma unroll
    for (int ci = 0; ci < 32; ci++)
        st[(ci*8 + w)*33 + lane] = vals[ci];
    __syncthreads();

    #pragma unroll
    for (int p = 0; p < 4; p++) {
        int t = (threadIdx.x >> 5) + p*8;
        float r = rs[t];
        __half* orow = g_hn_h + (size_t)(l0 + t)*DMODEL;
        #pragma unroll
        for (int j = 0; j < 8; j++) {
            int c = lane + j*32;
            orow[c] = __float2half(st[c*33 + t] * r * nw[c]);
        }
    }
}

// ---------------- fp16 tensor-core GEMM: C = A(MxK) * B(NxK)^T --------------
#define HBUF 3840   // words per buffer (A 128*20 + B 64*20)

template<int MODE>
__global__ __launch_bounds__(256) void mma_pipe_h(
    const __half* __restrict__ A, const __half* __restrict__ Bw,
    float* __restrict__ C, int K, int N, const float* __restrict__ resid)
{
    extern __shared__ __align__(16) unsigned sm[];
    int tid  = threadIdx.x;
    int lane = tid & 31, w = tid >> 5;
    int wm = w & 3, wn = w >> 2;
    int rowBase = blockIdx.x * 128;
    int colBase = blockIdx.y * 64;

    int arow = tid >> 1, aseg = tid & 1;
    int brow = tid >> 2, bseg = tid & 3;
    const __half* Ag = A  + (size_t)(rowBase + arow)*K + aseg*16;
    const __half* Bg = Bw + (size_t)(colBase + brow)*K + bseg*8;

    float acc[2][4][4];
    #pragma unroll
    for (int mt = 0; mt < 2; mt++)
        #pragma unroll
        for (int nt = 0; nt < 4; nt++)
            #pragma unroll
            for (int q = 0; q < 4; q++) acc[mt][nt][q] = 0.f;

    unsigned sbase = (unsigned)__cvta_generic_to_shared(sm);

    auto issue = [&](int kt, int buf) {
        unsigned ab = sbase + (unsigned)buf*15360u;
        cpa16(ab + (unsigned)(arow*80 + aseg*32),      Ag + kt);
        cpa16(ab + (unsigned)(arow*80 + aseg*32 + 16), Ag + kt + 8);
        cpa16(ab + 10240u + (unsigned)(brow*80 + bseg*16), Bg + kt);
        asm volatile("cp.async.commit_group;\n");
    };

    int CH = K >> 5;
    issue(0, 0);

    for (int c = 0; c < CH; c++) {
        if (c + 1 < CH) {
            issue((c+1)*32, (c+1)&1);
            asm volatile("cp.async.wait_group 1;\n");
        } else {
            asm volatile("cp.async.wait_group 0;\n");
        }
        __syncthreads();

        const unsigned* Asw = sm + (c&1)*HBUF;
        const unsigned* Bsw = Asw + 2560;

        #pragma unroll
        for (int ks = 0; ks < 2; ks++) {
            int kw = ks*8;
            unsigned a[2][4], bq[4][2];
            #pragma unroll
            for (int mt = 0; mt < 2; mt++) {
                int r0 = wm*32 + mt*16 + (lane >> 2);
                int bi = r0*20 + kw + (lane & 3);
                a[mt][0] = Asw[bi];
                a[mt][1] = Asw[bi + 160];
                a[mt][2] = Asw[bi + 4];
                a[mt][3] = Asw[bi + 164];
            }
            #pragma unroll
            for (int nt = 0; nt < 4; nt++) {
                int n0 = wn*32 + nt*8 + (lane >> 2);
                int bb = n0*20 + kw + (lane & 3);
                bq[nt][0] = Bsw[bb];
                bq[nt][1] = Bsw[bb + 4];
            }
            #pragma unroll
            for (int mt = 0; mt < 2; mt++)
                #pragma unroll
                for (int nt = 0; nt < 4; nt++)
                    asm volatile(
                        "mma.sync.aligned.m16n8k16.row.col.f32.f16.f16.f32 "
                        "{%0,%1,%2,%3}, {%4,%5,%6,%7}, {%8,%9}, {%0,%1,%2,%3};"
                        : "+f"(acc[mt][nt][0]), "+f"(acc[mt][nt][1]),
                          "+f"(acc[mt][nt][2]), "+f"(acc[mt][nt][3])
                        : "r"(a[mt][0]), "r"(a[mt][1]), "r"(a[mt][2]), "r"(a[mt][3]),
                          "r"(bq[nt][0]), "r"(bq[nt][1]));
        }
        __syncthreads();
    }

    if (MODE == 0) {
        #pragma unroll
        for (int mt = 0; mt < 2; mt++) {
            #pragma unroll
            for (int nt = 0; nt < 4; nt++) {
                int r0 = rowBase + wm*32 + mt*16 + (lane >> 2);
                int c0 = colBase + wn*32 + nt*8 + (lane & 3)*2;
                *(float2*)&C[(size_t)r0*N + c0] =
                    make_float2(acc[mt][nt][0], acc[mt][nt][1]);
                *(float2*)&C[(size_t)(r0+8)*N + c0] =
                    make_float2(acc[mt][nt][2], acc[mt][nt][3]);
            }
        }
    } else {
        float* tr = (float*)sm;              // [64 c][132]
        #pragma unroll
        for (int mt = 0; mt < 2; mt++) {
            #pragma unroll
            for (int nt = 0; nt < 4; nt++) {
                int r  = wm*32 + mt*16 + (lane >> 2);
                int cl = wn*32 + nt*8 + (lane & 3)*2;
                tr[ cl   *132 + r    ] = acc[mt][nt][0];
                tr[(cl+1)*132 + r    ] = acc[mt][nt][1];
                tr[ cl   *132 + r + 8] = acc[mt][nt][2];
                tr[(cl+1)*132 + r + 8] = acc[mt][nt][3];
            }
        }
        __syncthreads();
        int b0 = rowBase >> 11;
        int lbase = rowBase & 2047;
        for (int i = tid; i < 64*32; i += 256) {
            int cl = i >> 5, j = i & 31;
            float4 v = *(float4*)&tr[cl*132 + j*4];
            size_t o = (size_t)b0*DMODEL*SEQ + (size_t)(colBase + cl)*SEQ + lbase + j*4;
            float4 rr = *(const float4*)&resid[o];
            v.x += rr.x; v.y += rr.y; v.z += rr.z; v.w += rr.w;
            *(float4*)&C[o] = v;
        }
    }
}

// ---------------- x_proj fused with conv+SiLU (fp16 MMA, B resident) --------
// Block = 32 tokens. x_proj_w (fp16) loaded to smem ONCE; K-loop stages
// conv+silu A tiles (double buffered) with register-prefetched loads.
#define XPB 260   // words per B row in smem

__global__ __launch_bounds__(256) void xproj_conv_kernel(
    const float* __restrict__ cw, const float* __restrict__ cb)
{
    extern __shared__ __align__(16) unsigned xsm[];
    unsigned* Bs = xsm;                 // [64][XPB] words (rows 48+ unused)
    unsigned* As = xsm + 64*XPB;        // 2 x [32][20] words

    int tid = threadIdx.x, lane = tid & 31, w = tid >> 5;
    int rowBase = blockIdx.x * 32;
    int l0 = rowBase & 2047;

    // load all of x_proj_w fp16 into smem (48 rows x 512 halfs)
    {
        unsigned bbase = (unsigned)__cvta_generic_to_shared(Bs);
        #pragma unroll
        for (int k = 0; k < 12; k++) {
            int i = tid + k*256;            // 16B chunk id, 64 per row
            int n = i >> 6;
            int hc = (i & 63) * 8;
            cpa16(bbase + (unsigned)((n*XPB + (hc >> 1))*4),
                  g_wxp_h + (size_t)n*DINNER + hc);
        }
        asm volatile("cp.async.commit_group;\n");
    }

    int tA   = tid >> 3;
    int dOff = (tid & 7) * 4;
    int gt   = rowBase + tA;

    // prefetch conv inputs for chunk 0
    float4 v[4];
    #pragma unroll
    for (int j = 0; j < 4; j++) {
        int ls = l0 + tA - 3 + j;
        v[j] = (ls >= 0) ? *(const float4*)(g_xz + (size_t)(gt-3+j)*1024 + dOff)
                         : make_float4(0.f,0.f,0.f,0.f);
    }

    float acc[2][4];
    #pragma unroll
    for (int mt = 0; mt < 2; mt++)
        #pragma unroll
        for (int q = 0; q < 4; q++) acc[mt][q] = 0.f;

    asm volatile("cp.async.wait_group 0;\n");
    __syncthreads();

    for (int c = 0; c < 16; c++) {
        int d = c*32 + dOff;
        // conv + silu
        float4 w0 = *(const float4*)(cw + (size_t)d*4);
        float4 w1 = *(const float4*)(cw + (size_t)(d+1)*4);
        float4 w2 = *(const float4*)(cw + (size_t)(d+2)*4);
        float4 w3 = *(const float4*)(cw + (size_t)(d+3)*4);
        float4 a4 = *(const float4*)(cb + d);
        a4.x += w0.x*v[0].x + w0.y*v[1].x + w0.z*v[2].x + w0.w*v[3].x;
        a4.y += w1.x*v[0].y + w1.y*v[1].y + w1.z*v[2].y + w1.w*v[3].y;
        a4.z += w2.x*v[0].z + w2.y*v[1].z + w2.z*v[2].z + w2.w*v[3].z;
        a4.w += w3.x*v[0].w + w3.y*v[1].w + w3.z*v[2].w + w3.w*v[3].w;
        a4.x = a4.x / (1.f + __expf(-a4.x));
        a4.y = a4.y / (1.f + __expf(-a4.y));
        a4.z = a4.z / (1.f + __expf(-a4.z));
        a4.w = a4.w / (1.f + __expf(-a4.w));
        *(float4*)(g_xc + (size_t)gt*DINNER + d) = a4;

        // pack to fp16 and stage into A buffer
        unsigned* Ab = As + (c & 1)*640;
        __half2 p01 = __floats2half2_rn(a4.x, a4.y);
        __half2 p23 = __floats2half2_rn(a4.z, a4.w);
        Ab[tA*20 + (dOff >> 1)    ] = *(unsigned*)&p01;
        Ab[tA*20 + (dOff >> 1) + 1] = *(unsigned*)&p23;

        // prefetch next chunk
        if (c + 1 < 16) {
            int dn = (c+1)*32 + dOff;
            #pragma unroll
            for (int j = 0; j < 4; j++) {
                int ls = l0 + tA - 3 + j;
                v[j] = (ls >= 0) ? *(const float4*)(g_xz + (size_t)(gt-3+j)*1024 + dn)
                                 : make_float4(0.f,0.f,0.f,0.f);
            }
        }
        __syncthreads();

        // MMA: 2 k16 steps
        const unsigned* Asw = As + (c & 1)*640;
        #pragma unroll
        for (int ks = 0; ks < 2; ks++) {
            int kw = ks*8;
            unsigned a[2][4], bq[2];
            #pragma unroll
            for (int mt = 0; mt < 2; mt++) {
                int r0 = mt*16 + (lane >> 2);
                int bi = r0*20 + kw + (lane & 3);
                a[mt][0] = Asw[bi];
                a[mt][1] = Asw[bi + 160];
                a[mt][2] = Asw[bi + 4];
                a[mt][3] = Asw[bi + 164];
            }
            {
                int n0 = w*8 + (lane >> 2);
                int bb = n0*XPB + c*16 + kw + (lane & 3);
                bq[0] = Bs[bb];
                bq[1] = Bs[bb + 4];
            }
            #pragma unroll
            for (int mt = 0; mt < 2; mt++)
                asm volatile(
                    "mma.sync.aligned.m16n8k16.row.col.f32.f16.f16.f32 "
                    "{%0,%1,%2,%3}, {%4,%5,%6,%7}, {%8,%9}, {%0,%1,%2,%3};"
                    : "+f"(acc[mt][0]), "+f"(acc[mt][1]),
                      "+f"(acc[mt][2]), "+f"(acc[mt][3])
                    : "r"(a[mt][0]), "r"(a[mt][1]), "r"(a[mt][2]), "r"(a[mt][3]),
                      "r"(bq[0]), "r"(bq[1]));
        }
    }

    #pragma unroll
    for (int mt = 0; mt < 2; mt++) {
        int r0 = rowBase + mt*16 + (lane >> 2);
        int c0 = w*8 + (lane & 3)*2;
        if (c0 < 48) {
            *(float2*)&g_dbl[(size_t)r0*48 + c0] = make_float2(acc[mt][0], acc[mt][1]);
            *(float2*)&g_dbl[(size_t)(r0+8)*48 + c0] = make_float2(acc[mt][2], acc[mt][3]);
        }
    }
}

// ---------------- selective scan: fused dt_proj + cp.async double buffer ----
__global__ __launch_bounds__(128) void scan_kernel(
    const float* __restrict__ A_log, const float* __restrict__ Dp,
    const float* __restrict__ dtW, const float* __restrict__ dtB)
{
    int b   = blockIdx.y;
    int d0  = blockIdx.x * 8;
    int tid = threadIdx.x;
    int dl  = tid >> 4, n = tid & 15;
    int d   = d0 + dl;

    float a = -expf(A_log[d*DSTATE + n]);
    float h = 0.f;
    float Dval = Dp[d0 + (tid & 7)];

    __shared__ float sdbl[2][32][52];
    __shared__ float sxc[2][32][8];
    __shared__ float sz[2][32][8];
    __shared__ float sdelta[32][8];
    __shared__ float sdx[32][8];
    __shared__ float shc[32][128];
    __shared__ float sW[128];
    __shared__ float sbias[8];

    sW[tid] = dtW[(size_t)(d0 + (tid >> 4))*16 + (tid & 15)];
    if (tid < 8) sbias[tid] = dtB[d0 + tid];

    unsigned adbl = (unsigned)__cvta_generic_to_shared(&sdbl[0][0][0]);
    unsigned axc  = (unsigned)__cvta_generic_to_shared(&sxc[0][0][0]);
    unsigned az   = (unsigned)__cvta_generic_to_shared(&sz[0][0][0]);

    auto issue = [&](int ch, int buf) {
        int base = b*SEQ + ch*32;
        #pragma unroll
        for (int k = 0; k < 3; k++) {
            int i = tid + k*128;
            int t = i / 12, s = i % 12;
            cpa16(adbl + (unsigned)((buf*32*52 + t*52 + s*4)*4),
                  g_dbl + (size_t)(base + t)*48 + s*4);
        }
        if (tid < 64) {
            int t = tid >> 1, hf = tid & 1;
            cpa16(axc + (unsigned)((buf*256 + t*8 + hf*4)*4),
                  g_xc + (size_t)(base + t)*DINNER + d0 + hf*4);
        } else {
            int i = tid - 64;
            int t = i >> 1, hf = i & 1;
            cpa16(az + (unsigned)((buf*256 + t*8 + hf*4)*4),
                  g_xz + (size_t)(base + t)*1024 + DINNER + d0 + hf*4);
        }
        asm volatile("cp.async.commit_group;\n");
    };

    issue(0, 0);

    for (int ch = 0; ch < 64; ch++) {
        if (ch + 1 < 64) {
            issue(ch + 1, (ch + 1) & 1);
            asm volatile("cp.async.wait_group 1;\n");
        } else {
            asm volatile("cp.async.wait_group 0;\n");
        }
        __syncthreads();
        int buf = ch & 1;

        // delta = softplus(dt . W + bias), also precompute delta*x
        #pragma unroll
        for (int k = 0; k < 2; k++) {
            int i = tid + k*128;
            int t = i >> 3, dd = i & 7;
            float acc = sbias[dd];
            const float* row = sdbl[buf][t];
            const float* wv  = &sW[dd*16];
            #pragma unroll
            for (int r = 0; r < 16; r++) acc = fmaf(row[r], wv[r], acc);
            acc = (acc > 20.f) ? acc : log1pf(__expf(acc));
            sdelta[t][dd] = acc;
            sdx[t][dd] = acc * sxc[buf][t][dd];
        }
        __syncthreads();

        // recurrence (h chain in registers)
        #pragma unroll
        for (int t = 0; t < 32; t++) {
            float dA = __expf(sdelta[t][dl] * a);
            h = fmaf(dA, h, sdx[t][dl] * sdbl[buf][t][16 + n]);
            shc[t][tid] = h * sdbl[buf][t][32 + n];
        }
        __syncthreads();

        // reduce over n + D skip + gate, store fp16
        #pragma unroll
        for (int k = 0; k < 2; k++) {
            int i = tid + k*128;
            int t = i >> 3, dd = i & 7;
            float s = 0.f;
            #pragma unroll
            for (int q = 0; q < 16; q++) s += shc[t][dd*16 + q];
            float yv = fmaf(sxc[buf][t][dd], Dval, s);
            float zv = sz[buf][t][dd];
            yv *= zv / (1.f + __expf(-zv));
            g_yact_h[(size_t)(b*SEQ + ch*32 + t)*DINNER + d0 + dd] = __float2half(yv);
        }
        __syncthreads();
    }
}

// ---------------- launch ----------------
extern "C" void kernel_launch(void* const* d_in, const int* in_sizes, int n_in,
                              void* d_out, int out_size)
{
    const float* x          = (const float*)d_in[0];
    const float* norm_w     = (const float*)d_in[1];
    const float* in_proj_w  = (const float*)d_in[2];
    const float* conv_w     = (const float*)d_in[3];
    const float* conv_b     = (const float*)d_in[4];
    const float* x_proj_w   = (const float*)d_in[5];
    const float* dt_proj_w  = (const float*)d_in[6];
    const float* dt_proj_b  = (const float*)d_in[7];
    const float* A_log      = (const float*)d_in[8];
    const float* Dp         = (const float*)d_in[9];
    const float* out_proj_w = (const float*)d_in[10];
    float* out = (float*)d_out;
    (void)in_sizes; (void)n_in; (void)out_size;

    __half *hn_h, *yact_h, *win_h, *wout_h;
    float *xz;
    cudaGetSymbolAddress((void**)&hn_h,   g_hn_h);
    cudaGetSymbolAddress((void**)&xz,     g_xz);
    cudaGetSymbolAddress((void**)&yact_h, g_yact_h);
    cudaGetSymbolAddress((void**)&win_h,  g_win_h);
    cudaGetSymbolAddress((void**)&wout_h, g_wout_h);

    const int SMEM = 34816;
    const int XSMEM = (64*XPB + 2*640) * 4;   // 71680
    cudaFuncSetAttribute(mma_pipe_h<0>, cudaFuncAttributeMaxDynamicSharedMemorySize, SMEM);
    cudaFuncSetAttribute(mma_pipe_h<1>, cudaFuncAttributeMaxDynamicSharedMemorySize, SMEM);
    cudaFuncSetAttribute(xproj_conv_kernel, cudaFuncAttributeMaxDynamicSharedMemorySize, XSMEM);

    // 0) weights -> fp16
    cvt_weights<<<(2*DINNER*DMODEL + 255)/256, 256>>>(in_proj_w, out_proj_w, x_proj_w);
    // 1) rmsnorm (fp16 out)
    rmsnorm_kernel<<<NTOK/32, 256>>>(x, norm_w);
    // 2) xz = hn @ in_proj_w^T  (fp16 mma)
    mma_pipe_h<0><<<dim3(32, 16), 256, SMEM>>>(hn_h, win_h, xz, DMODEL, 2*DINNER, nullptr);
    // 3+4) xc = silu(conv(xin)); dbl = xc @ x_proj_w^T (fused, fp16 mma, B resident)
    xproj_conv_kernel<<<NTOK/32, 256, XSMEM>>>(conv_w, conv_b);
    // 5+6) delta (fused dt_proj) + selective scan + gate (fp16 out)
    scan_kernel<<<dim3(DINNER/8, BATCH), 128>>>(A_log, Dp, dt_proj_w, dt_proj_b);
    // 7) out = yact @ out_proj_w^T + residual (fp16 mma, transposed store)
    mma_pipe_h<1><<<dim3(32, 4), 256, SMEM>>>(yact_h, wout_h, out, DINNER, DMODEL, x);
}

// round 7
// speedup vs baseline: 2.0185x; 1.3612x over previous
#include <cuda_runtime.h>
#include <cuda_fp16.h>
#include <math.h>

#define BATCH  2
#define SEQ    2048
#define DMODEL 256
#define DINNER 512
#define DSTATE 16
#define NTOK   (BATCH*SEQ)   // 4096
#define NSEG   8
#define SEGLEN (SEQ/NSEG)    // 256
#define NCHAIN (BATCH*DINNER*DSTATE)  // 16384

// ---------------- scratch ----------------
__device__ __half g_hn_h[NTOK*DMODEL];
__device__ float  g_xz[NTOK*2*DINNER];
__device__ float  g_xc[NTOK*DINNER];
__device__ float  g_dbl[NTOK*48];
__device__ __half g_yact_h[NTOK*DINNER];
__device__ __half g_win_h[2*DINNER*DMODEL];
__device__ __half g_wout_h[DMODEL*DINNER];
__device__ __half g_wxp_h[48*DINNER];
__device__ float  g_scanH[NSEG*NCHAIN];
__device__ float  g_scanP[NSEG*NCHAIN];
__device__ float  g_carry[NSEG*NCHAIN];

__device__ __forceinline__ void cpa16(unsigned dst, const void* src) {
    asm volatile("cp.async.ca.shared.global [%0], [%1], 16;\n" :: "r"(dst), "l"(src));
}

// ---------------- 0) weight conversion fp32 -> fp16 ----------------
__global__ __launch_bounds__(256) void cvt_weights(
    const float* __restrict__ win, const float* __restrict__ wout,
    const float* __restrict__ wxp)
{
    int i = blockIdx.x*256 + threadIdx.x;
    if (i < 2*DINNER*DMODEL) g_win_h[i] = __float2half(win[i]);
    if (i < DMODEL*DINNER)   g_wout_h[i] = __float2half(wout[i]);
    if (i < 48*DINNER)       g_wxp_h[i] = __float2half(wxp[i]);
}

// ---------------- 1) RMSNorm ----------------
__global__ __launch_bounds__(256) void rmsnorm_kernel(
    const float* __restrict__ x, const float* __restrict__ nw)
{
    int l0 = blockIdx.x * 32;
    int b  = l0 >> 11;
    int lb = l0 & 2047;
    int w    = threadIdx.x >> 5;
    int lane = threadIdx.x & 31;

    __shared__ float st[256*33];
    __shared__ float ssum[32][9];
    __shared__ float rs[32];

    const float* xb = x + (size_t)b * DMODEL * SEQ + lb + lane;

    float vals[32];
    float ss = 0.f;
    #pragma unroll
    for (int ci = 0; ci < 32; ci++) {
        int c = ci*8 + w;
        float v = xb[(size_t)c * SEQ];
        vals[ci] = v;
        ss += v*v;
    }
    ssum[lane][w] = ss;
    __syncthreads();
    if (threadIdx.x < 32) {
        float tot = 0.f;
        #pragma unroll
        for (int j = 0; j < 8; j++) tot += ssum[threadIdx.x][j];
        rs[threadIdx.x] = rsqrtf(tot * (1.0f/DMODEL) + 1e-5f);
    }
    #pragma unroll
    for (int ci = 0; ci < 32; ci++)
        st[(ci*8 + w)*33 + lane] = vals[ci];
    __syncthreads();

    #pragma unroll
    for (int p = 0; p < 4; p++) {
        int t = (threadIdx.x >> 5) + p*8;
        float r = rs[t];
        __half* orow = g_hn_h + (size_t)(l0 + t)*DMODEL;
        #pragma unroll
        for (int j = 0; j < 8; j++) {
            int c = lane + j*32;
            orow[c] = __float2half(st[c*33 + t] * r * nw[c]);
        }
    }
}

// ---------------- fp16 tensor-core GEMM ----------------
#define HBUF 3840

template<int MODE>
__global__ __launch_bounds__(256) void mma_pipe_h(
    const __half* __restrict__ A, const __half* __restrict__ Bw,
    float* __restrict__ C, int K, int N, const float* __restrict__ resid)
{
    extern __shared__ __align__(16) unsigned sm[];
    int tid  = threadIdx.x;
    int lane = tid & 31, w = tid >> 5;
    int wm = w & 3, wn = w >> 2;
    int rowBase = blockIdx.x * 128;
    int colBase = blockIdx.y * 64;

    int arow = tid >> 1, aseg = tid & 1;
    int brow = tid >> 2, bseg = tid & 3;
    const __half* Ag = A  + (size_t)(rowBase + arow)*K + aseg*16;
    const __half* Bg = Bw + (size_t)(colBase + brow)*K + bseg*8;

    float acc[2][4][4];
    #pragma unroll
    for (int mt = 0; mt < 2; mt++)
        #pragma unroll
        for (int nt = 0; nt < 4; nt++)
            #pragma unroll
            for (int q = 0; q < 4; q++) acc[mt][nt][q] = 0.f;

    unsigned sbase = (unsigned)__cvta_generic_to_shared(sm);

    auto issue = [&](int kt, int buf) {
        unsigned ab = sbase + (unsigned)buf*15360u;
        cpa16(ab + (unsigned)(arow*80 + aseg*32),      Ag + kt);
        cpa16(ab + (unsigned)(arow*80 + aseg*32 + 16), Ag + kt + 8);
        cpa16(ab + 10240u + (unsigned)(brow*80 + bseg*16), Bg + kt);
        asm volatile("cp.async.commit_group;\n");
    };

    int CH = K >> 5;
    issue(0, 0);

    for (int c = 0; c < CH; c++) {
        if (c + 1 < CH) {
            issue((c+1)*32, (c+1)&1);
            asm volatile("cp.async.wait_group 1;\n");
        } else {
            asm volatile("cp.async.wait_group 0;\n");
        }
        __syncthreads();

        const unsigned* Asw = sm + (c&1)*HBUF;
        const unsigned* Bsw = Asw + 2560;

        #pragma unroll
        for (int ks = 0; ks < 2; ks++) {
            int kw = ks*8;
            unsigned a[2][4], bq[4][2];
            #pragma unroll
            for (int mt = 0; mt < 2; mt++) {
                int r0 = wm*32 + mt*16 + (lane >> 2);
                int bi = r0*20 + kw + (lane & 3);
                a[mt][0] = Asw[bi];
                a[mt][1] = Asw[bi + 160];
                a[mt][2] = Asw[bi + 4];
                a[mt][3] = Asw[bi + 164];
            }
            #pragma unroll
            for (int nt = 0; nt < 4; nt++) {
                int n0 = wn*32 + nt*8 + (lane >> 2);
                int bb = n0*20 + kw + (lane & 3);
                bq[nt][0] = Bsw[bb];
                bq[nt][1] = Bsw[bb + 4];
            }
            #pragma unroll
            for (int mt = 0; mt < 2; mt++)
                #pragma unroll
                for (int nt = 0; nt < 4; nt++)
                    asm volatile(
                        "mma.sync.aligned.m16n8k16.row.col.f32.f16.f16.f32 "
                        "{%0,%1,%2,%3}, {%4,%5,%6,%7}, {%8,%9}, {%0,%1,%2,%3};"
                        : "+f"(acc[mt][nt][0]), "+f"(acc[mt][nt][1]),
                          "+f"(acc[mt][nt][2]), "+f"(acc[mt][nt][3])
                        : "r"(a[mt][0]), "r"(a[mt][1]), "r"(a[mt][2]), "r"(a[mt][3]),
                          "r"(bq[nt][0]), "r"(bq[nt][1]));
        }
        __syncthreads();
    }

    if (MODE == 0) {
        #pragma unroll
        for (int mt = 0; mt < 2; mt++) {
            #pragma unroll
            for (int nt = 0; nt < 4; nt++) {
                int r0 = rowBase + wm*32 + mt*16 + (lane >> 2);
                int c0 = colBase + wn*32 + nt*8 + (lane & 3)*2;
                *(float2*)&C[(size_t)r0*N + c0] =
                    make_float2(acc[mt][nt][0], acc[mt][nt][1]);
                *(float2*)&C[(size_t)(r0+8)*N + c0] =
                    make_float2(acc[mt][nt][2], acc[mt][nt][3]);
            }
        }
    } else {
        float* tr = (float*)sm;
        #pragma unroll
        for (int mt = 0; mt < 2; mt++) {
            #pragma unroll
            for (int nt = 0; nt < 4; nt++) {
                int r  = wm*32 + mt*16 + (lane >> 2);
                int cl = wn*32 + nt*8 + (lane & 3)*2;
                tr[ cl   *132 + r    ] = acc[mt][nt][0];
                tr[(cl+1)*132 + r    ] = acc[mt][nt][1];
                tr[ cl   *132 + r + 8] = acc[mt][nt][2];
                tr[(cl+1)*132 + r + 8] = acc[mt][nt][3];
            }
        }
        __syncthreads();
        int b0 = rowBase >> 11;
        int lbase = rowBase & 2047;
        for (int i = tid; i < 64*32; i += 256) {
            int cl = i >> 5, j = i & 31;
            float4 v = *(float4*)&tr[cl*132 + j*4];
            size_t o = (size_t)b0*DMODEL*SEQ + (size_t)(colBase + cl)*SEQ + lbase + j*4;
            float4 rr = *(const float4*)&resid[o];
            v.x += rr.x; v.y += rr.y; v.z += rr.z; v.w += rr.w;
            *(float4*)&C[o] = v;
        }
    }
}

// ---------------- x_proj fused with conv+SiLU ----------------
#define XPB 260

__global__ __launch_bounds__(256) void xproj_conv_kernel(
    const float* __restrict__ cw, const float* __restrict__ cb)
{
    extern __shared__ __align__(16) unsigned xsm[];
    unsigned* Bs = xsm;
    unsigned* As = xsm + 64*XPB;

    int tid = threadIdx.x, lane = tid & 31, w = tid >> 5;
    int rowBase = blockIdx.x * 32;
    int l0 = rowBase & 2047;

    {
        unsigned bbase = (unsigned)__cvta_generic_to_shared(Bs);
        #pragma unroll
        for (int k = 0; k < 12; k++) {
            int i = tid + k*256;
            int n = i >> 6;
            int hc = (i & 63) * 8;
            cpa16(bbase + (unsigned)((n*XPB + (hc >> 1))*4),
                  g_wxp_h + (size_t)n*DINNER + hc);
        }
        asm volatile("cp.async.commit_group;\n");
    }

    int tA   = tid >> 3;
    int dOff = (tid & 7) * 4;
    int gt   = rowBase + tA;

    float4 v[4];
    #pragma unroll
    for (int j = 0; j < 4; j++) {
        int ls = l0 + tA - 3 + j;
        v[j] = (ls >= 0) ? *(const float4*)(g_xz + (size_t)(gt-3+j)*1024 + dOff)
                         : make_float4(0.f,0.f,0.f,0.f);
    }

    float acc[2][4];
    #pragma unroll
    for (int mt = 0; mt < 2; mt++)
        #pragma unroll
        for (int q = 0; q < 4; q++) acc[mt][q] = 0.f;

    asm volatile("cp.async.wait_group 0;\n");
    __syncthreads();

    for (int c = 0; c < 16; c++) {
        int d = c*32 + dOff;
        float4 w0 = *(const float4*)(cw + (size_t)d*4);
        float4 w1 = *(const float4*)(cw + (size_t)(d+1)*4);
        float4 w2 = *(const float4*)(cw + (size_t)(d+2)*4);
        float4 w3 = *(const float4*)(cw + (size_t)(d+3)*4);
        float4 a4 = *(const float4*)(cb + d);
        a4.x += w0.x*v[0].x + w0.y*v[1].x + w0.z*v[2].x + w0.w*v[3].x;
        a4.y += w1.x*v[0].y + w1.y*v[1].y + w1.z*v[2].y + w1.w*v[3].y;
        a4.z += w2.x*v[0].z + w2.y*v[1].z + w2.z*v[2].z + w2.w*v[3].z;
        a4.w += w3.x*v[0].w + w3.y*v[1].w + w3.z*v[2].w + w3.w*v[3].w;
        a4.x = a4.x / (1.f + __expf(-a4.x));
        a4.y = a4.y / (1.f + __expf(-a4.y));
        a4.z = a4.z / (1.f + __expf(-a4.z));
        a4.w = a4.w / (1.f + __expf(-a4.w));
        *(float4*)(g_xc + (size_t)gt*DINNER + d) = a4;

        unsigned* Ab = As + (c & 1)*640;
        __half2 p01 = __floats2half2_rn(a4.x, a4.y);
        __half2 p23 = __floats2half2_rn(a4.z, a4.w);
        Ab[tA*20 + (dOff >> 1)    ] = *(unsigned*)&p01;
        Ab[tA*20 + (dOff >> 1) + 1] = *(unsigned*)&p23;

        if (c + 1 < 16) {
            int dn = (c+1)*32 + dOff;
            #pragma unroll
            for (int j = 0; j < 4; j++) {
                int ls = l0 + tA - 3 + j;
                v[j] = (ls >= 0) ? *(const float4*)(g_xz + (size_t)(gt-3+j)*1024 + dn)
                                 : make_float4(0.f,0.f,0.f,0.f);
            }
        }
        __syncthreads();

        const unsigned* Asw = As + (c & 1)*640;
        #pragma unroll
        for (int ks = 0; ks < 2; ks++) {
            int kw = ks*8;
            unsigned a[2][4], bq[2];
            #pragma unroll
            for (int mt = 0; mt < 2; mt++) {
                int r0 = mt*16 + (lane >> 2);
                int bi = r0*20 + kw + (lane & 3);
                a[mt][0] = Asw[bi];
                a[mt][1] = Asw[bi + 160];
                a[mt][2] = Asw[bi + 4];
                a[mt][3] = Asw[bi + 164];
            }
            {
                int n0 = w*8 + (lane >> 2);
                int bb = n0*XPB + c*16 + kw + (lane & 3);
                bq[0] = Bs[bb];
                bq[1] = Bs[bb + 4];
            }
            #pragma unroll
            for (int mt = 0; mt < 2; mt++)
                asm volatile(
                    "mma.sync.aligned.m16n8k16.row.col.f32.f16.f16.f32 "
                    "{%0,%1,%2,%3}, {%4,%5,%6,%7}, {%8,%9}, {%0,%1,%2,%3};"
                    : "+f"(acc[mt][0]), "+f"(acc[mt][1]),
                      "+f"(acc[mt][2]), "+f"(acc[mt][3])
                    : "r"(a[mt][0]), "r"(a[mt][1]), "r"(a[mt][2]), "r"(a[mt][3]),
                      "r"(bq[0]), "r"(bq[1]));
        }
    }

    #pragma unroll
    for (int mt = 0; mt < 2; mt++) {
        int r0 = rowBase + mt*16 + (lane >> 2);
        int c0 = w*8 + (lane & 3)*2;
        if (c0 < 48) {
            *(float2*)&g_dbl[(size_t)r0*48 + c0] = make_float2(acc[mt][0], acc[mt][1]);
            *(float2*)&g_dbl[(size_t)(r0+8)*48 + c0] = make_float2(acc[mt][2], acc[mt][3]);
        }
    }
}

// ---------------- segmented selective scan ----------------
// chain index = (b*DINNER + d)*DSTATE + n  (0..16383)
// Phase 1: per-segment local recurrence from h=0, store (P=prod dA, H=local h).
__global__ __launch_bounds__(128) void scan_part1(
    const float* __restrict__ A_log,
    const float* __restrict__ dtW, const float* __restrict__ dtB)
{
    int b   = blockIdx.z;
    int seg = blockIdx.y;
    int d0  = blockIdx.x * 8;
    int tid = threadIdx.x;
    int dl  = tid >> 4, n = tid & 15;
    int d   = d0 + dl;

    float a = -expf(A_log[d*DSTATE + n]);
    float h = 0.f, P = 1.f;

    __shared__ float sdbl[2][32][52];
    __shared__ float sxc[2][32][8];
    __shared__ float sdelta[32][8];
    __shared__ float sdx[32][8];
    __shared__ float sW[128];
    __shared__ float sbias[8];

    sW[tid] = dtW[(size_t)(d0 + (tid >> 4))*16 + (tid & 15)];
    if (tid < 8) sbias[tid] = dtB[d0 + tid];

    unsigned adbl = (unsigned)__cvta_generic_to_shared(&sdbl[0][0][0]);
    unsigned axc  = (unsigned)__cvta_generic_to_shared(&sxc[0][0][0]);

    auto issue = [&](int ch, int buf) {
        int base = b*SEQ + seg*SEGLEN + ch*32;
        #pragma unroll
        for (int k = 0; k < 3; k++) {
            int i = tid + k*128;
            int t = i / 12, s = i % 12;
            cpa16(adbl + (unsigned)((buf*32*52 + t*52 + s*4)*4),
                  g_dbl + (size_t)(base + t)*48 + s*4);
        }
        if (tid < 64) {
            int t = tid >> 1, hf = tid & 1;
            cpa16(axc + (unsigned)((buf*256 + t*8 + hf*4)*4),
                  g_xc + (size_t)(base + t)*DINNER + d0 + hf*4);
        }
        asm volatile("cp.async.commit_group;\n");
    };

    issue(0, 0);

    for (int ch = 0; ch < SEGLEN/32; ch++) {
        if (ch + 1 < SEGLEN/32) {
            issue(ch + 1, (ch + 1) & 1);
            asm volatile("cp.async.wait_group 1;\n");
        } else {
            asm volatile("cp.async.wait_group 0;\n");
        }
        __syncthreads();
        int buf = ch & 1;

        #pragma unroll
        for (int k = 0; k < 2; k++) {
            int i = tid + k*128;
            int t = i >> 3, dd = i & 7;
            float acc = sbias[dd];
            const float* row = sdbl[buf][t];
            const float* wv  = &sW[dd*16];
            #pragma unroll
            for (int r = 0; r < 16; r++) acc = fmaf(row[r], wv[r], acc);
            acc = (acc > 20.f) ? acc : log1pf(__expf(acc));
            sdelta[t][dd] = acc;
            sdx[t][dd] = acc * sxc[buf][t][dd];
        }
        __syncthreads();

        #pragma unroll
        for (int t = 0; t < 32; t++) {
            float dA = __expf(sdelta[t][dl] * a);
            h = fmaf(dA, h, sdx[t][dl] * sdbl[buf][t][16 + n]);
            P *= dA;
        }
        __syncthreads();
    }

    int chain = (b*DINNER + d)*DSTATE + n;
    g_scanH[seg*NCHAIN + chain] = h;
    g_scanP[seg*NCHAIN + chain] = P;
}

// Phase 2: serial carry composition over 8 segments per chain.
__global__ __launch_bounds__(256) void scan_carry_kernel()
{
    int chain = blockIdx.x*256 + threadIdx.x;
    float carry = 0.f;
    #pragma unroll
    for (int s = 0; s < NSEG; s++) {
        g_carry[s*NCHAIN + chain] = carry;
        carry = g_scanP[s*NCHAIN + chain]*carry + g_scanH[s*NCHAIN + chain];
    }
}

// Phase 3: full recurrence from carry, reduce over n + D skip + gate.
__global__ __launch_bounds__(128) void scan_part3(
    const float* __restrict__ A_log, const float* __restrict__ Dp,
    const float* __restrict__ dtW, const float* __restrict__ dtB)
{
    int b   = blockIdx.z;
    int seg = blockIdx.y;
    int d0  = blockIdx.x * 8;
    int tid = threadIdx.x;
    int dl  = tid >> 4, n = tid & 15;
    int d   = d0 + dl;

    float a = -expf(A_log[d*DSTATE + n]);
    float h = g_carry[seg*NCHAIN + (b*DINNER + d)*DSTATE + n];
    float Dval = Dp[d0 + (tid & 7)];

    __shared__ float sdbl[2][32][52];
    __shared__ float sxc[2][32][8];
    __shared__ float sz[2][32][8];
    __shared__ float sdelta[32][8];
    __shared__ float sdx[32][8];
    __shared__ float shc[32][128];
    __shared__ float sW[128];
    __shared__ float sbias[8];

    sW[tid] = dtW[(size_t)(d0 + (tid >> 4))*16 + (tid & 15)];
    if (tid < 8) sbias[tid] = dtB[d0 + tid];

    unsigned adbl = (unsigned)__cvta_generic_to_shared(&sdbl[0][0][0]);
    unsigned axc  = (unsigned)__cvta_generic_to_shared(&sxc[0][0][0]);
    unsigned az   = (unsigned)__cvta_generic_to_shared(&sz[0][0][0]);

    auto issue = [&](int ch, int buf) {
        int base = b*SEQ + seg*SEGLEN + ch*32;
        #pragma unroll
        for (int k = 0; k < 3; k++) {
            int i = tid + k*128;
            int t = i / 12, s = i % 12;
            cpa16(adbl + (unsigned)((buf*32*52 + t*52 + s*4)*4),
                  g_dbl + (size_t)(base + t)*48 + s*4);
        }
        if (tid < 64) {
            int t = tid >> 1, hf = tid & 1;
            cpa16(axc + (unsigned)((buf*256 + t*8 + hf*4)*4),
                  g_xc + (size_t)(base + t)*DINNER + d0 + hf*4);
        } else {
            int i = tid - 64;
            int t = i >> 1, hf = i & 1;
            cpa16(az + (unsigned)((buf*256 + t*8 + hf*4)*4),
                  g_xz + (size_t)(base + t)*1024 + DINNER + d0 + hf*4);
        }
        asm volatile("cp.async.commit_group;\n");
    };

    issue(0, 0);

    for (int ch = 0; ch < SEGLEN/32; ch++) {
        if (ch + 1 < SEGLEN/32) {
            issue(ch + 1, (ch + 1) & 1);
            asm volatile("cp.async.wait_group 1;\n");
        } else {
            asm volatile("cp.async.wait_group 0;\n");
        }
        __syncthreads();
        int buf = ch & 1;

        #pragma unroll
        for (int k = 0; k < 2; k++) {
            int i = tid + k*128;
            int t = i >> 3, dd = i & 7;
            float acc = sbias[dd];
            const float* row = sdbl[buf][t];
            const float* wv  = &sW[dd*16];
            #pragma unroll
            for (int r = 0; r < 16; r++) acc = fmaf(row[r], wv[r], acc);
            acc = (acc > 20.f) ? acc : log1pf(__expf(acc));
            sdelta[t][dd] = acc;
            sdx[t][dd] = acc * sxc[buf][t][dd];
        }
        __syncthreads();

        #pragma unroll
        for (int t = 0; t < 32; t++) {
            float dA = __expf(sdelta[t][dl] * a);
            h = fmaf(dA, h, sdx[t][dl] * sdbl[buf][t][16 + n]);
            shc[t][tid] = h * sdbl[buf][t][32 + n];
        }
        __syncthreads();

        #pragma unroll
        for (int k = 0; k < 2; k++) {
            int i = tid + k*128;
            int t = i >> 3, dd = i & 7;
            float s = 0.f;
            #pragma unroll
            for (int q = 0; q < 16; q++) s += shc[t][dd*16 + q];
            float yv = fmaf(sxc[buf][t][dd], Dval, s);
            float zv = sz[buf][t][dd];
            yv *= zv / (1.f + __expf(-zv));
            g_yact_h[(size_t)(b*SEQ + seg*SEGLEN + ch*32 + t)*DINNER + d0 + dd] = __float2half(yv);
        }
        __syncthreads();
    }
}

// ---------------- launch ----------------
extern "C" void kernel_launch(void* const* d_in, const int* in_sizes, int n_in,
                              void* d_out, int out_size)
{
    const float* x          = (const float*)d_in[0];
    const float* norm_w     = (const float*)d_in[1];
    const float* in_proj_w  = (const float*)d_in[2];
    const float* conv_w     = (const float*)d_in[3];
    const float* conv_b     = (const float*)d_in[4];
    const float* x_proj_w   = (const float*)d_in[5];
    const float* dt_proj_w  = (const float*)d_in[6];
    const float* dt_proj_b  = (const float*)d_in[7];
    const float* A_log      = (const float*)d_in[8];
    const float* Dp         = (const float*)d_in[9];
    const float* out_proj_w = (const float*)d_in[10];
    float* out = (float*)d_out;
    (void)in_sizes; (void)n_in; (void)out_size;

    __half *hn_h, *yact_h, *win_h, *wout_h;
    float *xz;
    cudaGetSymbolAddress((void**)&hn_h,   g_hn_h);
    cudaGetSymbolAddress((void**)&xz,     g_xz);
    cudaGetSymbolAddress((void**)&yact_h, g_yact_h);
    cudaGetSymbolAddress((void**)&win_h,  g_win_h);
    cudaGetSymbolAddress((void**)&wout_h, g_wout_h);

    const int SMEM0 = 30720;
    const int SMEM1 = 34816;
    const int XSMEM = (64*XPB + 2*640) * 4;
    cudaFuncSetAttribute(mma_pipe_h<0>, cudaFuncAttributeMaxDynamicSharedMemorySize, SMEM0);
    cudaFuncSetAttribute(mma_pipe_h<1>, cudaFuncAttributeMaxDynamicSharedMemorySize, SMEM1);
    cudaFuncSetAttribute(xproj_conv_kernel, cudaFuncAttributeMaxDynamicSharedMemorySize, XSMEM);

    // 0) weights -> fp16
    cvt_weights<<<(2*DINNER*DMODEL + 255)/256, 256>>>(in_proj_w, out_proj_w, x_proj_w);
    // 1) rmsnorm (fp16 out)
    rmsnorm_kernel<<<NTOK/32, 256>>>(x, norm_w);
    // 2) xz = hn @ in_proj_w^T
    mma_pipe_h<0><<<dim3(32, 16), 256, SMEM0>>>(hn_h, win_h, xz, DMODEL, 2*DINNER, nullptr);
    // 3+4) conv+silu fused with x_proj GEMM
    xproj_conv_kernel<<<NTOK/32, 256, XSMEM>>>(conv_w, conv_b);
    // 5+6) segmented selective scan (3 phases)
    scan_part1<<<dim3(DINNER/8, NSEG, BATCH), 128>>>(A_log, dt_proj_w, dt_proj_b);
    scan_carry_kernel<<<NCHAIN/256, 256>>>();
    scan_part3<<<dim3(DINNER/8, NSEG, BATCH), 128>>>(A_log, Dp, dt_proj_w, dt_proj_b);
    // 7) out = yact @ out_proj_w^T + residual
    mma_pipe_h<1><<<dim3(32, 4), 256, SMEM1>>>(yact_h, wout_h, out, DINNER, DMODEL, x);
}